// round 1
// baseline (speedup 1.0000x reference)
#include <cuda_runtime.h>
#include <math.h>

#define BATCH 4
#define SEQ 1024
#define DIM 256
#define NH 8
#define DH 32
#define ROWS (BATCH*SEQ)      // 4096
#define MAXN 256
#define FFH 512

// ---------------- scratch (static device globals; no allocation) ----------------
__device__ float g_hp [ROWS*DIM];        // 4 MB  projected features (layers 0/1)
__device__ float g_hp2[ROWS*NH*DIM];     // 32 MB projected features (layer 2)
__device__ float g_h  [ROWS*DIM];        // 4 MB  current hidden state
__device__ float g_tmp[ROWS*DIM];        // 4 MB  GAT output before residual
__device__ float g_ln [ROWS*DIM];        // 4 MB  layernorm output
__device__ float g_ffh[ROWS*FFH];        // 8 MB  FFN hidden
__device__ float g_src[ROWS*NH];
__device__ float g_dst[ROWS*NH];
__device__ int   g_nbr[ROWS*MAXN];
__device__ int   g_cnt[ROWS];

// ---------------- neighbor list build (deterministic ordered compaction) --------
__global__ void build_nbr(const float* __restrict__ adj){
    int row = blockIdx.x;                       // b*SEQ + i
    const float* arow = adj + (size_t)row * SEQ;
    __shared__ int cnt;
    __shared__ int wcnt[8], wbase[8];
    int tid = threadIdx.x, warp = tid >> 5, lane = tid & 31;
    if (tid == 0) cnt = 0;
    __syncthreads();
    for (int base = 0; base < SEQ; base += 256){
        int j = base + tid;
        bool p = arow[j] > 0.f;
        unsigned m = __ballot_sync(0xffffffffu, p);
        if (lane == 0) wcnt[warp] = __popc(m);
        __syncthreads();
        if (tid == 0){ int s = cnt; for (int w = 0; w < 8; w++){ wbase[w] = s; s += wcnt[w]; } cnt = s; }
        __syncthreads();
        if (p){
            int pos = wbase[warp] + __popc(m & ((1u << lane) - 1u));
            if (pos < MAXN) g_nbr[row*MAXN + pos] = j;
        }
        __syncthreads();
    }
    if (tid == 0) g_cnt[row] = cnt < MAXN ? cnt : MAXN;
}

// ---------------- tiled SGEMM: C[M,N] = A[M,K] @ B[K,N] (+ epilogue) ------------
// EPI: 0 = plain, 1 = +bias then GELU(tanh approx), 2 = +bias + residual
#define BM 64
#define BN 64
#define BK 16
template<int EPI>
__global__ __launch_bounds__(256)
void sgemm(const float* __restrict__ A, const float* __restrict__ Bm,
           const float* __restrict__ bias, const float* __restrict__ res,
           float* __restrict__ C, int M, int N, int K){
    __shared__ float As[BK][BM];
    __shared__ float Bs[BK][BN];
    int tid = threadIdx.x;
    int bm = blockIdx.y * BM, bn = blockIdx.x * BN;
    int tx = tid & 15, ty = tid >> 4;           // 16x16 threads, 4x4 micro-tile
    float acc[4][4] = {};
    for (int k0 = 0; k0 < K; k0 += BK){
        #pragma unroll
        for (int i = 0; i < 4; i++){
            int e = tid + i*256;
            int ar = e >> 4, ak = e & 15;
            As[ak][ar] = A[(size_t)(bm + ar)*K + k0 + ak];
        }
        #pragma unroll
        for (int i = 0; i < 4; i++){
            int e = tid + i*256;
            int bk = e >> 6, bc = e & 63;
            Bs[bk][bc] = Bm[(size_t)(k0 + bk)*N + bn + bc];
        }
        __syncthreads();
        #pragma unroll
        for (int k = 0; k < BK; k++){
            float ra[4], rb[4];
            #pragma unroll
            for (int i = 0; i < 4; i++) ra[i] = As[k][ty*4 + i];
            #pragma unroll
            for (int j = 0; j < 4; j++) rb[j] = Bs[k][tx*4 + j];
            #pragma unroll
            for (int i = 0; i < 4; i++)
                #pragma unroll
                for (int j = 0; j < 4; j++) acc[i][j] += ra[i]*rb[j];
        }
        __syncthreads();
    }
    #pragma unroll
    for (int i = 0; i < 4; i++){
        int r = bm + ty*4 + i;
        #pragma unroll
        for (int j = 0; j < 4; j++){
            int c = bn + tx*4 + j;
            float v = acc[i][j];
            if (EPI == 1){
                v += bias[c];
                float t = 0.7978845608028654f*(v + 0.044715f*v*v*v);
                v = 0.5f*v*(1.f + tanhf(t));
            } else if (EPI == 2){
                v += bias[c] + res[(size_t)r*N + c];
            }
            C[(size_t)r*N + c] = v;
        }
    }
}

// ---------------- per-node attention scores, layers 0/1 (dh=32) -----------------
__global__ void scores01(const float* __restrict__ a_src, const float* __restrict__ a_dst){
    int row = blockIdx.x;
    int tid = threadIdx.x;
    int h = tid >> 5, d = tid & 31;
    float v = g_hp[(size_t)row*DIM + h*DH + d];
    float s = v * a_src[h*DH + d];
    float t = v * a_dst[h*DH + d];
    #pragma unroll
    for (int o = 16; o > 0; o >>= 1){
        s += __shfl_down_sync(0xffffffffu, s, o);
        t += __shfl_down_sync(0xffffffffu, t, o);
    }
    if (d == 0){ g_src[row*NH + h] = s; g_dst[row*NH + h] = t; }
}

// ---------------- per-node attention scores, layer 2 (head dim = 256) -----------
__global__ void scores2(const float* __restrict__ a_src2, const float* __restrict__ a_dst2){
    int row = blockIdx.x;
    int tid = threadIdx.x;
    int h = tid >> 5, lane = tid & 31;
    const float* base = g_hp2 + ((size_t)row*NH + h)*DIM;
    float s = 0.f, t = 0.f;
    #pragma unroll
    for (int d = lane; d < DIM; d += 32){
        float v = base[d];
        s += v * a_src2[h*DIM + d];
        t += v * a_dst2[h*DIM + d];
    }
    #pragma unroll
    for (int o = 16; o > 0; o >>= 1){
        s += __shfl_down_sync(0xffffffffu, s, o);
        t += __shfl_down_sync(0xffffffffu, t, o);
    }
    if (lane == 0){ g_src[row*NH + h] = s; g_dst[row*NH + h] = t; }
}

// compute softmax weights for this row's neighbors into smem w[MAXN*NH]
__device__ __forceinline__ void compute_weights(int row, int b, int cnt,
                                                const int* nbr, float* w, float* srcI){
    int tid = threadIdx.x;
    if (tid < NH) srcI[tid] = g_src[row*NH + tid];
    __syncthreads();
    for (int idx = tid; idx < cnt*NH; idx += 256){
        int n = idx >> 3, h = idx & 7;
        float e = srcI[h] + g_dst[(size_t)(b*SEQ + nbr[n])*NH + h];
        w[n*NH + h] = e > 0.f ? e : 0.2f*e;    // LeakyReLU(0.2)
    }
    __syncthreads();
    int h = tid >> 5, lane = tid & 31;         // warp h does softmax for head h
    float m = -1e30f;
    for (int n = lane; n < cnt; n += 32) m = fmaxf(m, w[n*NH + h]);
    #pragma unroll
    for (int o = 16; o > 0; o >>= 1) m = fmaxf(m, __shfl_xor_sync(0xffffffffu, m, o));
    float ssum = 0.f;
    for (int n = lane; n < cnt; n += 32){
        float e = expf(w[n*NH + h] - m);
        w[n*NH + h] = e;
        ssum += e;
    }
    #pragma unroll
    for (int o = 16; o > 0; o >>= 1) ssum += __shfl_xor_sync(0xffffffffu, ssum, o);
    float inv = 1.f / ssum;
    for (int n = lane; n < cnt; n += 32) w[n*NH + h] *= inv;
    __syncthreads();
}

// ---------------- sparse attention aggregate, layers 0/1 ------------------------
__global__ __launch_bounds__(256)
void attn01(){
    int row = blockIdx.x;
    int b = row / SEQ;
    int tid = threadIdx.x;
    int cnt = g_cnt[row];
    __shared__ int   nbr[MAXN];
    __shared__ float w[MAXN*NH];
    __shared__ float srcI[NH];
    for (int n = tid; n < cnt; n += 256) nbr[n] = g_nbr[row*MAXN + n];
    __syncthreads();
    compute_weights(row, b, cnt, nbr, w, srcI);
    int ch = tid;                  // output channel 0..255
    int hh = ch >> 5;              // its head (dh=32 concat)
    float acc = 0.f;
    for (int n = 0; n < cnt; n++)
        acc += w[n*NH + hh] * g_hp[((size_t)(b*SEQ + nbr[n]))*DIM + ch];
    g_tmp[(size_t)row*DIM + ch] = acc;
}

// ---------------- sparse attention aggregate, layer 2 (mean over heads) ---------
__global__ __launch_bounds__(256)
void attn2(){
    int row = blockIdx.x;
    int b = row / SEQ;
    int tid = threadIdx.x;
    int cnt = g_cnt[row];
    __shared__ int   nbr[MAXN];
    __shared__ float w[MAXN*NH];
    __shared__ float srcI[NH];
    for (int n = tid; n < cnt; n += 256) nbr[n] = g_nbr[row*MAXN + n];
    __syncthreads();
    compute_weights(row, b, cnt, nbr, w, srcI);
    int ch = tid;
    float acc = 0.f;
    for (int n = 0; n < cnt; n++){
        size_t basep = ((size_t)(b*SEQ + nbr[n]))*NH*DIM + ch;
        const float* wp = &w[n*NH];
        #pragma unroll
        for (int hh = 0; hh < NH; hh++)
            acc += wp[hh] * g_hp2[basep + (size_t)hh*DIM];
    }
    g_tmp[(size_t)row*DIM + ch] = acc * 0.125f;   // mean over 8 heads
}

// ---------------- elementwise: residual + ELU / plain ---------------------------
__global__ void add_elu(const float* __restrict__ resid, float* __restrict__ out){
    int i = blockIdx.x*256 + threadIdx.x;
    float v = g_tmp[i] + resid[i];
    out[i] = v > 0.f ? v : expm1f(v);
}
__global__ void add_plain(const float* __restrict__ resid, float* __restrict__ out){
    int i = blockIdx.x*256 + threadIdx.x;
    out[i] = g_tmp[i] + resid[i];
}

// ---------------- LayerNorm (per row of 256) ------------------------------------
__global__ void layernorm(const float* __restrict__ ln_g, const float* __restrict__ ln_b){
    int row = blockIdx.x, tid = threadIdx.x;
    float v = g_h[(size_t)row*DIM + tid];
    __shared__ float red[8];
    __shared__ float mu, rstd;
    float s = v;
    #pragma unroll
    for (int o = 16; o > 0; o >>= 1) s += __shfl_xor_sync(0xffffffffu, s, o);
    if ((tid & 31) == 0) red[tid >> 5] = s;
    __syncthreads();
    if (tid == 0){ float t = 0.f; for (int i = 0; i < 8; i++) t += red[i]; mu = t / 256.f; }
    __syncthreads();
    float d = v - mu;
    s = d*d;
    #pragma unroll
    for (int o = 16; o > 0; o >>= 1) s += __shfl_xor_sync(0xffffffffu, s, o);
    if ((tid & 31) == 0) red[tid >> 5] = s;
    __syncthreads();
    if (tid == 0){ float t = 0.f; for (int i = 0; i < 8; i++) t += red[i]; rstd = rsqrtf(t/256.f + 1e-5f); }
    __syncthreads();
    g_ln[(size_t)row*DIM + tid] = d*rstd*ln_g[tid] + ln_b[tid];
}

// ---------------- launch ---------------------------------------------------------
extern "C" void kernel_launch(void* const* d_in, const int* in_sizes, int n_in,
                              void* d_out, int out_size){
    const float* adj    = (const float*)d_in[0];
    const float* x      = (const float*)d_in[1];
    const float* W0     = (const float*)d_in[2];
    const float* a_src0 = (const float*)d_in[3];
    const float* a_dst0 = (const float*)d_in[4];
    const float* W1     = (const float*)d_in[5];
    const float* a_src1 = (const float*)d_in[6];
    const float* a_dst1 = (const float*)d_in[7];
    const float* W2     = (const float*)d_in[8];
    const float* a_src2 = (const float*)d_in[9];
    const float* a_dst2 = (const float*)d_in[10];
    const float* ln_g   = (const float*)d_in[11];
    const float* ln_b   = (const float*)d_in[12];
    const float* ff_w1  = (const float*)d_in[13];
    const float* ff_b1  = (const float*)d_in[14];
    const float* ff_w2  = (const float*)d_in[15];
    const float* ff_b2  = (const float*)d_in[16];
    float* out = (float*)d_out;

    float *p_hp, *p_hp2, *p_h, *p_ln, *p_ffh;
    cudaGetSymbolAddress((void**)&p_hp,  g_hp);
    cudaGetSymbolAddress((void**)&p_hp2, g_hp2);
    cudaGetSymbolAddress((void**)&p_h,   g_h);
    cudaGetSymbolAddress((void**)&p_ln,  g_ln);
    cudaGetSymbolAddress((void**)&p_ffh, g_ffh);

    dim3 blk(256);
    // neighbor lists from dense adjacency
    build_nbr<<<ROWS, blk>>>(adj);

    // ---- GAT layer 0 ----
    sgemm<0><<<dim3(DIM/BN, ROWS/BM), blk>>>(x, W0, nullptr, nullptr, p_hp, ROWS, DIM, DIM);
    scores01<<<ROWS, blk>>>(a_src0, a_dst0);
    attn01<<<ROWS, blk>>>();
    add_elu<<<ROWS*DIM/256, blk>>>(x, p_h);

    // ---- GAT layer 1 ----
    sgemm<0><<<dim3(DIM/BN, ROWS/BM), blk>>>(p_h, W1, nullptr, nullptr, p_hp, ROWS, DIM, DIM);
    scores01<<<ROWS, blk>>>(a_src1, a_dst1);
    attn01<<<ROWS, blk>>>();
    add_elu<<<ROWS*DIM/256, blk>>>(p_h, p_h);

    // ---- GAT layer 2 (mean heads) ----
    sgemm<0><<<dim3(NH*DIM/BN, ROWS/BM), blk>>>(p_h, W2, nullptr, nullptr, p_hp2, ROWS, NH*DIM, DIM);
    scores2<<<ROWS, blk>>>(a_src2, a_dst2);
    attn2<<<ROWS, blk>>>();
    add_plain<<<ROWS*DIM/256, blk>>>(p_h, p_h);

    // ---- LayerNorm ----
    layernorm<<<ROWS, blk>>>(ln_g, ln_b);

    // ---- FFN (GELU) + residual ----
    sgemm<1><<<dim3(FFH/BN, ROWS/BM), blk>>>(p_ln, ff_w1, ff_b1, nullptr, p_ffh, ROWS, FFH, DIM);
    sgemm<2><<<dim3(DIM/BN, ROWS/BM), blk>>>(p_ffh, ff_w2, ff_b2, p_ln, out, ROWS, DIM, FFH);
}

// round 2
// speedup vs baseline: 1.0701x; 1.0701x over previous
#include <cuda_runtime.h>
#include <math.h>

#define BATCH 4
#define SEQ 1024
#define DIM 256
#define NH 8
#define DH 32
#define ROWS (BATCH*SEQ)      // 4096
#define MAXN 256
#define FFH 512
#define HD2 (NH*DIM)          // 2048

// ---------------- scratch (static device globals; no allocation) ----------------
__device__ float g_hp [ROWS*DIM];        // projected features (layers 0/1)
__device__ float g_h  [ROWS*DIM];        // current hidden state
__device__ float g_tmp[ROWS*DIM];        // pre-LN buffer
__device__ float g_ln [ROWS*DIM];        // layernorm output
__device__ float g_ffh[ROWS*FFH];        // FFN hidden
__device__ float g_agg[ROWS*HD2];        // layer-2 per-head aggregated h (32 MB)
__device__ float g_w2p[HD2*DIM];         // permuted W2 (mean folded)
__device__ float g_va_src[NH*DIM];
__device__ float g_va_dst[NH*DIM];
__device__ float g_src[ROWS*NH];
__device__ float g_dst[ROWS*NH];
__device__ int   g_nbr[ROWS*MAXN];
__device__ int   g_cnt[ROWS];

// ---------------- neighbor list build (deterministic ordered compaction) --------
__global__ void build_nbr(const float* __restrict__ adj){
    int row = blockIdx.x;
    const float* arow = adj + (size_t)row * SEQ;
    __shared__ int cnt;
    __shared__ int wcnt[8], wbase[8];
    int tid = threadIdx.x, warp = tid >> 5, lane = tid & 31;
    if (tid == 0) cnt = 0;
    __syncthreads();
    for (int base = 0; base < SEQ; base += 256){
        int j = base + tid;
        bool p = arow[j] > 0.f;
        unsigned m = __ballot_sync(0xffffffffu, p);
        if (lane == 0) wcnt[warp] = __popc(m);
        __syncthreads();
        if (tid == 0){ int s = cnt; for (int w = 0; w < 8; w++){ wbase[w] = s; s += wcnt[w]; } cnt = s; }
        __syncthreads();
        if (p){
            int pos = wbase[warp] + __popc(m & ((1u << lane) - 1u));
            if (pos < MAXN) g_nbr[row*MAXN + pos] = j;
        }
        __syncthreads();
    }
    if (tid == 0) g_cnt[row] = cnt < MAXN ? cnt : MAXN;
}

// ---------------- W2 prep: permuted W2 (mean folded) + attention vectors --------
__global__ void w2perm(const float* __restrict__ W2){
    int idx = blockIdx.x*256 + threadIdx.x;       // < 2048*256
    int hc = idx >> 8, k = idx & 255;
    int h = hc >> 8, c = hc & 255;
    g_w2p[idx] = 0.125f * W2[(size_t)c*HD2 + h*DIM + k];
}

__global__ void va_compute(const float* __restrict__ W2,
                           const float* __restrict__ as2, const float* __restrict__ ad2){
    int gw = blockIdx.x*8 + (threadIdx.x >> 5);   // 0..2047 -> (h,c)
    int lane = threadIdx.x & 31;
    int h = gw >> 8, c = gw & 255;
    float s = 0.f, t = 0.f;
    #pragma unroll
    for (int d = lane; d < DIM; d += 32){
        float wv = W2[(size_t)c*HD2 + h*DIM + d];
        s += wv * as2[h*DIM + d];
        t += wv * ad2[h*DIM + d];
    }
    #pragma unroll
    for (int o = 16; o > 0; o >>= 1){
        s += __shfl_down_sync(0xffffffffu, s, o);
        t += __shfl_down_sync(0xffffffffu, t, o);
    }
    if (lane == 0){ g_va_src[h*DIM + c] = s; g_va_dst[h*DIM + c] = t; }
}

// ---------------- tiled SGEMM 128 x TBN, BK=8, double-buffered ------------------
// EPI: 0 plain, 1 +bias GELU, 2 +bias+res, 3 +res
template<int EPI, int TBN>
__global__ __launch_bounds__(256)
void sgemm2(const float* __restrict__ A, const float* __restrict__ B,
            const float* __restrict__ bias, const float* __restrict__ res,
            float* __restrict__ C, int M, int N, int K){
    constexpr int TBM = 128, TBK = 8, JT = TBN/16;
    __shared__ float As[2][TBK][TBM];
    __shared__ float Bs[2][TBK][TBN];
    int tid = threadIdx.x;
    int bm = blockIdx.y*TBM, bn = blockIdx.x*TBN;
    int tx = tid & 15, ty = tid >> 4;
    int arow = tid >> 1, ak = (tid & 1)*4;
    bool bload = tid < TBK*TBN/4;
    int brow = tid / (TBN/4), bc4 = (tid % (TBN/4))*4;
    const float* Ap = A + (size_t)bm*K;
    const float* Bp = B + bn;
    {
        float4 a0 = *(const float4*)&Ap[(size_t)arow*K + ak];
        As[0][ak+0][arow]=a0.x; As[0][ak+1][arow]=a0.y; As[0][ak+2][arow]=a0.z; As[0][ak+3][arow]=a0.w;
        if (bload){
            float4 b0 = *(const float4*)&Bp[(size_t)brow*N + bc4];
            *(float4*)&Bs[0][brow][bc4] = b0;
        }
    }
    __syncthreads();
    float acc[8][JT] = {};
    int buf = 0;
    for (int k0 = 0; k0 < K; k0 += TBK){
        bool has = (k0 + TBK) < K;
        float4 na, nb;
        if (has){
            na = *(const float4*)&Ap[(size_t)arow*K + k0 + TBK + ak];
            if (bload) nb = *(const float4*)&Bp[(size_t)(k0 + TBK + brow)*N + bc4];
        }
        #pragma unroll
        for (int k = 0; k < TBK; k++){
            float ra[8], rb[JT];
            *(float4*)&ra[0] = *(const float4*)&As[buf][k][ty*8];
            *(float4*)&ra[4] = *(const float4*)&As[buf][k][ty*8+4];
            #pragma unroll
            for (int j4 = 0; j4 < JT; j4 += 4)
                *(float4*)&rb[j4] = *(const float4*)&Bs[buf][k][tx*JT + j4];
            #pragma unroll
            for (int i = 0; i < 8; i++)
                #pragma unroll
                for (int j = 0; j < JT; j++) acc[i][j] += ra[i]*rb[j];
        }
        if (has){
            int nbuf = buf ^ 1;
            As[nbuf][ak+0][arow]=na.x; As[nbuf][ak+1][arow]=na.y; As[nbuf][ak+2][arow]=na.z; As[nbuf][ak+3][arow]=na.w;
            if (bload) *(float4*)&Bs[nbuf][brow][bc4] = nb;
            __syncthreads();
            buf = nbuf;
        }
    }
    #pragma unroll
    for (int i = 0; i < 8; i++){
        int r = bm + ty*8 + i;
        size_t base = (size_t)r*N + bn + tx*JT;
        float vout[JT];
        #pragma unroll
        for (int j = 0; j < JT; j++){
            float v = acc[i][j];
            int cidx = bn + tx*JT + j;
            if (EPI == 1){
                v += bias[cidx];
                float t = 0.7978845608028654f*(v + 0.044715f*v*v*v);
                v = 0.5f*v*(1.f + tanhf(t));
            } else if (EPI == 2){
                v += bias[cidx] + res[base + j];
            } else if (EPI == 3){
                v += res[base + j];
            }
            vout[j] = v;
        }
        #pragma unroll
        for (int j4 = 0; j4 < JT; j4 += 4)
            *(float4*)&C[base + j4] = *(float4*)&vout[j4];
    }
}

// ---------------- per-node attention scores, layers 0/1 (dh=32) -----------------
__global__ void scores01(const float* __restrict__ a_src, const float* __restrict__ a_dst){
    int row = blockIdx.x;
    int tid = threadIdx.x;
    int h = tid >> 5, d = tid & 31;
    float v = g_hp[(size_t)row*DIM + h*DH + d];
    float s = v * a_src[h*DH + d];
    float t = v * a_dst[h*DH + d];
    #pragma unroll
    for (int o = 16; o > 0; o >>= 1){
        s += __shfl_down_sync(0xffffffffu, s, o);
        t += __shfl_down_sync(0xffffffffu, t, o);
    }
    if (d == 0){ g_src[row*NH + h] = s; g_dst[row*NH + h] = t; }
}

// ---------------- per-node attention scores, layer 2 (folded through W2) --------
__global__ void scores2b(){
    int row = blockIdx.x;
    int h = threadIdx.x >> 5, lane = threadIdx.x & 31;
    const float* hr = g_h + (size_t)row*DIM;
    float s = 0.f, t = 0.f;
    #pragma unroll
    for (int d = lane; d < DIM; d += 32){
        float v = hr[d];
        s += v * g_va_src[h*DIM + d];
        t += v * g_va_dst[h*DIM + d];
    }
    #pragma unroll
    for (int o = 16; o > 0; o >>= 1){
        s += __shfl_down_sync(0xffffffffu, s, o);
        t += __shfl_down_sync(0xffffffffu, t, o);
    }
    if (lane == 0){ g_src[row*NH + h] = s; g_dst[row*NH + h] = t; }
}

// softmax weights for this row's neighbors into smem w[MAXN*NH]
__device__ __forceinline__ void compute_weights(int row, int b, int cnt,
                                                const int* nbr, float* w, float* srcI){
    int tid = threadIdx.x;
    if (tid < NH) srcI[tid] = g_src[row*NH + tid];
    __syncthreads();
    for (int idx = tid; idx < cnt*NH; idx += 256){
        int n = idx >> 3, h = idx & 7;
        float e = srcI[h] + g_dst[(size_t)(b*SEQ + nbr[n])*NH + h];
        w[n*NH + h] = e > 0.f ? e : 0.2f*e;
    }
    __syncthreads();
    int h = tid >> 5, lane = tid & 31;
    float m = -1e30f;
    for (int n = lane; n < cnt; n += 32) m = fmaxf(m, w[n*NH + h]);
    #pragma unroll
    for (int o = 16; o > 0; o >>= 1) m = fmaxf(m, __shfl_xor_sync(0xffffffffu, m, o));
    float ssum = 0.f;
    for (int n = lane; n < cnt; n += 32){
        float e = expf(w[n*NH + h] - m);
        w[n*NH + h] = e;
        ssum += e;
    }
    #pragma unroll
    for (int o = 16; o > 0; o >>= 1) ssum += __shfl_xor_sync(0xffffffffu, ssum, o);
    float inv = 1.f / ssum;
    for (int n = lane; n < cnt; n += 32) w[n*NH + h] *= inv;
    __syncthreads();
}

// ---------------- sparse attention aggregate + residual + ELU, layers 0/1 -------
__global__ __launch_bounds__(256)
void attn01(const float* __restrict__ resid, float* __restrict__ out){
    int row = blockIdx.x;
    int b = row / SEQ;
    int tid = threadIdx.x;
    int cnt = g_cnt[row];
    __shared__ int   nbr[MAXN];
    __shared__ float w[MAXN*NH];
    __shared__ float srcI[NH];
    for (int n = tid; n < cnt; n += 256) nbr[n] = g_nbr[row*MAXN + n];
    __syncthreads();
    compute_weights(row, b, cnt, nbr, w, srcI);
    int ch = tid;
    int hh = ch >> 5;
    float acc = 0.f;
    for (int n = 0; n < cnt; n++)
        acc += w[n*NH + hh] * g_hp[((size_t)(b*SEQ + nbr[n]))*DIM + ch];
    float v = acc + resid[(size_t)row*DIM + ch];
    out[(size_t)row*DIM + ch] = v > 0.f ? v : expm1f(v);
}

// ---------------- layer 2: aggregate h per head (before W2) ---------------------
__global__ __launch_bounds__(256)
void attn2b(){
    int row = blockIdx.x;
    int b = row / SEQ;
    int tid = threadIdx.x;
    int cnt = g_cnt[row];
    __shared__ int   nbr[MAXN];
    __shared__ float w[MAXN*NH];
    __shared__ float srcI[NH];
    for (int n = tid; n < cnt; n += 256) nbr[n] = g_nbr[row*MAXN + n];
    __syncthreads();
    compute_weights(row, b, cnt, nbr, w, srcI);
    int c = tid;
    float acc[NH] = {};
    for (int n = 0; n < cnt; n++){
        float v = g_h[(size_t)(b*SEQ + nbr[n])*DIM + c];
        const float* wp = &w[n*NH];
        #pragma unroll
        for (int h = 0; h < NH; h++) acc[h] += wp[h]*v;
    }
    #pragma unroll
    for (int h = 0; h < NH; h++)
        g_agg[(size_t)row*HD2 + h*DIM + c] = acc[h];
}

// ---------------- LayerNorm ------------------------------------------------------
__global__ void layernorm(const float* __restrict__ in,
                          const float* __restrict__ ln_g, const float* __restrict__ ln_b,
                          float* __restrict__ out){
    int row = blockIdx.x, tid = threadIdx.x;
    float v = in[(size_t)row*DIM + tid];
    __shared__ float red[8];
    __shared__ float mu, rstd;
    float s = v;
    #pragma unroll
    for (int o = 16; o > 0; o >>= 1) s += __shfl_xor_sync(0xffffffffu, s, o);
    if ((tid & 31) == 0) red[tid >> 5] = s;
    __syncthreads();
    if (tid == 0){ float t = 0.f; for (int i = 0; i < 8; i++) t += red[i]; mu = t / 256.f; }
    __syncthreads();
    float d = v - mu;
    s = d*d;
    #pragma unroll
    for (int o = 16; o > 0; o >>= 1) s += __shfl_xor_sync(0xffffffffu, s, o);
    if ((tid & 31) == 0) red[tid >> 5] = s;
    __syncthreads();
    if (tid == 0){ float t = 0.f; for (int i = 0; i < 8; i++) t += red[i]; rstd = rsqrtf(t/256.f + 1e-5f); }
    __syncthreads();
    out[(size_t)row*DIM + tid] = d*rstd*ln_g[tid] + ln_b[tid];
}

// ---------------- launch ---------------------------------------------------------
extern "C" void kernel_launch(void* const* d_in, const int* in_sizes, int n_in,
                              void* d_out, int out_size){
    const float* adj    = (const float*)d_in[0];
    const float* x      = (const float*)d_in[1];
    const float* W0     = (const float*)d_in[2];
    const float* a_src0 = (const float*)d_in[3];
    const float* a_dst0 = (const float*)d_in[4];
    const float* W1     = (const float*)d_in[5];
    const float* a_src1 = (const float*)d_in[6];
    const float* a_dst1 = (const float*)d_in[7];
    const float* W2     = (const float*)d_in[8];
    const float* a_src2 = (const float*)d_in[9];
    const float* a_dst2 = (const float*)d_in[10];
    const float* ln_g   = (const float*)d_in[11];
    const float* ln_b   = (const float*)d_in[12];
    const float* ff_w1  = (const float*)d_in[13];
    const float* ff_b1  = (const float*)d_in[14];
    const float* ff_w2  = (const float*)d_in[15];
    const float* ff_b2  = (const float*)d_in[16];
    float* out = (float*)d_out;

    float *p_hp, *p_h, *p_tmp, *p_ln, *p_ffh, *p_agg, *p_w2p;
    cudaGetSymbolAddress((void**)&p_hp,  g_hp);
    cudaGetSymbolAddress((void**)&p_h,   g_h);
    cudaGetSymbolAddress((void**)&p_tmp, g_tmp);
    cudaGetSymbolAddress((void**)&p_ln,  g_ln);
    cudaGetSymbolAddress((void**)&p_ffh, g_ffh);
    cudaGetSymbolAddress((void**)&p_agg, g_agg);
    cudaGetSymbolAddress((void**)&p_w2p, g_w2p);

    dim3 blk(256);
    build_nbr<<<ROWS, blk>>>(adj);
    w2perm<<<HD2*DIM/256, blk>>>(W2);
    va_compute<<<256, blk>>>(W2, a_src2, a_dst2);

    // ---- GAT layer 0 ----
    sgemm2<0,64><<<dim3(DIM/64, ROWS/128), blk>>>(x, W0, nullptr, nullptr, p_hp, ROWS, DIM, DIM);
    scores01<<<ROWS, blk>>>(a_src0, a_dst0);
    attn01<<<ROWS, blk>>>(x, p_h);

    // ---- GAT layer 1 ----
    sgemm2<0,64><<<dim3(DIM/64, ROWS/128), blk>>>(p_h, W1, nullptr, nullptr, p_hp, ROWS, DIM, DIM);
    scores01<<<ROWS, blk>>>(a_src1, a_dst1);
    attn01<<<ROWS, blk>>>(p_h, p_h);

    // ---- GAT layer 2 (restructured: aggregate h, then W2) ----
    scores2b<<<ROWS, blk>>>();
    attn2b<<<ROWS, blk>>>();
    sgemm2<3,64><<<dim3(DIM/64, ROWS/128), blk>>>(p_agg, p_w2p, nullptr, p_h, p_tmp, ROWS, DIM, HD2);

    // ---- LayerNorm ----
    layernorm<<<ROWS, blk>>>(p_tmp, ln_g, ln_b, p_ln);

    // ---- FFN (GELU) + residual ----
    sgemm2<1,128><<<dim3(FFH/128, ROWS/128), blk>>>(p_ln, ff_w1, ff_b1, nullptr, p_ffh, ROWS, FFH, DIM);
    sgemm2<2,64><<<dim3(DIM/64, ROWS/128), blk>>>(p_ffh, ff_w2, ff_b2, p_ln, out, ROWS, DIM, FFH);
}

// round 4
// speedup vs baseline: 1.8665x; 1.7442x over previous
#include <cuda_runtime.h>
#include <cuda_bf16.h>
#include <math.h>
#include <stdint.h>

#define BATCH 4
#define SEQ 1024
#define DIM 256
#define NH 8
#define DH 32
#define ROWS (BATCH*SEQ)      // 4096
#define MAXN 256
#define FFH 512
#define HD2 (NH*DIM)          // 2048

// ---------------- scratch (static device globals; no allocation) ----------------
__device__ float g_hp [ROWS*DIM];
__device__ float g_h  [ROWS*DIM];
__device__ float g_tmp[ROWS*DIM];
__device__ float g_ln [ROWS*DIM];
__device__ __nv_bfloat16 gA_hi[ROWS*HD2];   // activation A (hi), max K=2048 layout
__device__ __nv_bfloat16 gA_lo[ROWS*HD2];
__device__ __nv_bfloat16 gF_hi[ROWS*FFH];   // FFN hidden split
__device__ __nv_bfloat16 gF_lo[ROWS*FFH];
__device__ __nv_bfloat16 w0_hi[DIM*DIM],  w0_lo[DIM*DIM];    // [N,K] transposed weights
__device__ __nv_bfloat16 w1_hi[DIM*DIM],  w1_lo[DIM*DIM];
__device__ __nv_bfloat16 w2_hi[DIM*HD2],  w2_lo[DIM*HD2];    // permuted W2, mean folded
__device__ __nv_bfloat16 f1_hi[FFH*DIM],  f1_lo[FFH*DIM];
__device__ __nv_bfloat16 f2_hi[DIM*FFH],  f2_lo[DIM*FFH];
__device__ float g_va_src[NH*DIM];
__device__ float g_va_dst[NH*DIM];
__device__ float g_src[ROWS*NH];
__device__ float g_dst[ROWS*NH];
__device__ int   g_nbr[ROWS*MAXN];
__device__ int   g_cnt[ROWS];

// ---------------- helpers ---------------------------------------------------------
__device__ __forceinline__ uint32_t smem_u32(const void* p){
    uint32_t a;
    asm("{ .reg .u64 t; cvta.to.shared.u64 t, %1; cvt.u32.u64 %0, t; }" : "=r"(a) : "l"(p));
    return a;
}
__device__ __forceinline__ void split_val(float v, __nv_bfloat16& hi, __nv_bfloat16& lo){
    hi = __float2bfloat16(v);
    lo = __float2bfloat16(v - __bfloat162float(hi));
}
#define CPA16(dst, src) \
    asm volatile("cp.async.cg.shared.global [%0], [%1], 16;" :: "r"(dst), "l"(src) : "memory")
#define LDSM4(r0,r1,r2,r3,addr) \
    asm volatile("ldmatrix.sync.aligned.m8n8.x4.shared.b16 {%0,%1,%2,%3}, [%4];" \
        : "=r"(r0),"=r"(r1),"=r"(r2),"=r"(r3) : "r"(addr))

__device__ __forceinline__ void mma_bf16(float* c, const uint32_t* a, uint32_t b0, uint32_t b1){
    asm volatile("mma.sync.aligned.m16n8k16.row.col.f32.bf16.bf16.f32 "
        "{%0,%1,%2,%3}, {%4,%5,%6,%7}, {%8,%9}, {%0,%1,%2,%3};"
        : "+f"(c[0]),"+f"(c[1]),"+f"(c[2]),"+f"(c[3])
        : "r"(a[0]),"r"(a[1]),"r"(a[2]),"r"(a[3]), "r"(b0),"r"(b1));
}

// ---------------- HMMA split-bf16 GEMM: C[M,N] = A[M,K] @ Bt[N,K]^T ---------------
// EPI: 0 plain fp32; 1 +bias,GELU -> bf16 hi/lo; 2 +bias+res fp32; 3 +res fp32
template<int EPI, int TN>
__global__ __launch_bounds__(256)
void gemm_mma(const __nv_bfloat16* __restrict__ Ah, const __nv_bfloat16* __restrict__ Al,
              const __nv_bfloat16* __restrict__ Bh, const __nv_bfloat16* __restrict__ Bl,
              const float* __restrict__ bias, const float* __restrict__ res,
              float* __restrict__ C, __nv_bfloat16* __restrict__ Chi, __nv_bfloat16* __restrict__ Clo,
              int M, int N, int K){
    constexpr int LD   = 40;                 // padded row length (elements)
    constexpr int A_SZ = 128*LD*2;           // bytes per A matrix per buffer
    constexpr int B_SZ = TN*LD*2;
    constexpr int BUF  = 2*A_SZ + 2*B_SZ;
    constexpr int NB   = TN/16;              // n-blocks per warp
    constexpr int NP   = TN/32;              // n-block pairs per warp
    extern __shared__ char sm[];
    uint32_t sb = smem_u32(sm);
    int tid = threadIdx.x, lane = tid & 31, wid = tid >> 5;
    int bm = blockIdx.y*128, bn = blockIdx.x*TN;
    int wm = (wid & 3)*32, wn = (wid >> 2)*(TN/2);
    float acc[2][NB][4] = {};
    int nch = K >> 5;

    auto load_chunk = [&](int c, int b){
        uint32_t s0 = sb + b*BUF;
        int k0 = c*32;
        #pragma unroll
        for (int i = 0; i < 2; i++){
            int u = tid + i*256;
            int row = u >> 2, c8 = u & 3;
            uint32_t so = (uint32_t)(row*LD + c8*8)*2;
            size_t go = (size_t)(bm + row)*K + k0 + c8*8;
            CPA16(s0 + so,        Ah + go);
            CPA16(s0 + A_SZ + so, Al + go);
        }
        for (int u = tid; u < TN*4; u += 256){
            int row = u >> 2, c8 = u & 3;
            uint32_t so = (uint32_t)(row*LD + c8*8)*2;
            size_t go = (size_t)(bn + row)*K + k0 + c8*8;
            CPA16(s0 + 2*A_SZ + so,        Bh + go);
            CPA16(s0 + 2*A_SZ + B_SZ + so, Bl + go);
        }
        asm volatile("cp.async.commit_group;" ::: "memory");
    };

    load_chunk(0, 0);
    for (int c = 0; c < nch; c++){
        if (c + 1 < nch){
            load_chunk(c + 1, (c + 1) & 1);
            asm volatile("cp.async.wait_group 1;" ::: "memory");
        } else {
            asm volatile("cp.async.wait_group 0;" ::: "memory");
        }
        __syncthreads();
        uint32_t sA = sb + (c & 1)*BUF;
        uint32_t sB = sA + 2*A_SZ;
        #pragma unroll
        for (int kk = 0; kk < 32; kk += 16){
            uint32_t ah[2][4], al[2][4];
            #pragma unroll
            for (int mb = 0; mb < 2; mb++){
                uint32_t ad = sA + (uint32_t)(((wm + mb*16 + (lane & 15))*LD + kk + (lane >> 4)*8)*2);
                LDSM4(ah[mb][0],ah[mb][1],ah[mb][2],ah[mb][3], ad);
                LDSM4(al[mb][0],al[mb][1],al[mb][2],al[mb][3], ad + A_SZ);
            }
            #pragma unroll
            for (int p = 0; p < NP; p++){
                uint32_t bd = sB + (uint32_t)(((wn + p*16 + ((lane >> 4) << 3) + (lane & 7))*LD
                                              + kk + ((lane >> 3) & 1)*8)*2);
                uint32_t bh[4], bl[4];
                LDSM4(bh[0],bh[1],bh[2],bh[3], bd);
                LDSM4(bl[0],bl[1],bl[2],bl[3], bd + B_SZ);
                #pragma unroll
                for (int mb = 0; mb < 2; mb++){
                    #pragma unroll
                    for (int j = 0; j < 2; j++){
                        float* a_ = acc[mb][p*2 + j];
                        mma_bf16(a_, ah[mb], bh[2*j], bh[2*j+1]);
                        mma_bf16(a_, ah[mb], bl[2*j], bl[2*j+1]);
                        mma_bf16(a_, al[mb], bh[2*j], bh[2*j+1]);
                    }
                }
            }
        }
        __syncthreads();
    }

    // epilogue
    int g = lane >> 2, tg = lane & 3;
    #pragma unroll
    for (int mb = 0; mb < 2; mb++){
        #pragma unroll
        for (int nb = 0; nb < NB; nb++){
            float* a_ = acc[mb][nb];
            int r0 = bm + wm + mb*16 + g;
            int col = bn + wn + nb*8 + tg*2;
            #pragma unroll
            for (int e = 0; e < 4; e++){
                int r = (e < 2) ? r0 : r0 + 8;
                int cc = col + (e & 1);
                size_t ci = (size_t)r*N + cc;
                float v = a_[e];
                if (EPI == 0){
                    C[ci] = v;
                } else if (EPI == 1){
                    v += bias[cc];
                    float t = 0.7978845608028654f*(v + 0.044715f*v*v*v);
                    v = 0.5f*v*(1.f + tanhf(t));
                    __nv_bfloat16 hi, lo; split_val(v, hi, lo);
                    Chi[ci] = hi; Clo[ci] = lo;
                } else if (EPI == 2){
                    C[ci] = v + bias[cc] + res[ci];
                } else {
                    C[ci] = v + res[ci];
                }
            }
        }
    }
}

// ---------------- neighbor list build ------------------------------------------
__global__ void build_nbr(const float* __restrict__ adj){
    int row = blockIdx.x;
    const float* arow = adj + (size_t)row * SEQ;
    __shared__ int cnt;
    __shared__ int wcnt[8], wbase[8];
    int tid = threadIdx.x, warp = tid >> 5, lane = tid & 31;
    if (tid == 0) cnt = 0;
    __syncthreads();
    for (int base = 0; base < SEQ; base += 256){
        int j = base + tid;
        bool p = arow[j] > 0.f;
        unsigned m = __ballot_sync(0xffffffffu, p);
        if (lane == 0) wcnt[warp] = __popc(m);
        __syncthreads();
        if (tid == 0){ int s = cnt; for (int w = 0; w < 8; w++){ wbase[w] = s; s += wcnt[w]; } cnt = s; }
        __syncthreads();
        if (p){
            int pos = wbase[warp] + __popc(m & ((1u << lane) - 1u));
            if (pos < MAXN) g_nbr[row*MAXN + pos] = j;
        }
        __syncthreads();
    }
    if (tid == 0) g_cnt[row] = cnt < MAXN ? cnt : MAXN;
}

// ---------------- weight prep ----------------------------------------------------
__global__ void wsplit(const float* __restrict__ W, __nv_bfloat16* __restrict__ Th,
                       __nv_bfloat16* __restrict__ Tl, int K, int N, float scale){
    int idx = blockIdx.x*256 + threadIdx.x;
    int n = idx / K, k = idx - n*K;
    float v = scale * W[(size_t)k*N + n];
    split_val(v, Th[idx], Tl[idx]);
}
__global__ void w2split(const float* __restrict__ W2){
    int idx = blockIdx.x*256 + threadIdx.x;
    int c = idx >> 11, k = idx & 2047;
    int h = k >> 8, i = k & 255;
    float v = 0.125f * W2[(size_t)i*HD2 + h*DIM + c];
    split_val(v, w2_hi[idx], w2_lo[idx]);
}
__global__ void split_x(const float* __restrict__ x){
    int idx = blockIdx.x*256 + threadIdx.x;
    split_val(x[idx], gA_hi[idx], gA_lo[idx]);
}
__global__ void va_compute(const float* __restrict__ W2,
                           const float* __restrict__ as2, const float* __restrict__ ad2){
    int gw = blockIdx.x*8 + (threadIdx.x >> 5);
    int lane = threadIdx.x & 31;
    int h = gw >> 8, c = gw & 255;
    float s = 0.f, t = 0.f;
    #pragma unroll
    for (int d = lane; d < DIM; d += 32){
        float wv = W2[(size_t)c*HD2 + h*DIM + d];
        s += wv * as2[h*DIM + d];
        t += wv * ad2[h*DIM + d];
    }
    #pragma unroll
    for (int o = 16; o > 0; o >>= 1){
        s += __shfl_down_sync(0xffffffffu, s, o);
        t += __shfl_down_sync(0xffffffffu, t, o);
    }
    if (lane == 0){ g_va_src[h*DIM + c] = s; g_va_dst[h*DIM + c] = t; }
}

// ---------------- attention scores ----------------------------------------------
__global__ void scores01(const float* __restrict__ a_src, const float* __restrict__ a_dst){
    int row = blockIdx.x;
    int tid = threadIdx.x;
    int h = tid >> 5, d = tid & 31;
    float v = g_hp[(size_t)row*DIM + h*DH + d];
    float s = v * a_src[h*DH + d];
    float t = v * a_dst[h*DH + d];
    #pragma unroll
    for (int o = 16; o > 0; o >>= 1){
        s += __shfl_down_sync(0xffffffffu, s, o);
        t += __shfl_down_sync(0xffffffffu, t, o);
    }
    if (d == 0){ g_src[row*NH + h] = s; g_dst[row*NH + h] = t; }
}
__global__ void scores2b(){
    int row = blockIdx.x;
    int h = threadIdx.x >> 5, lane = threadIdx.x & 31;
    const float* hr = g_h + (size_t)row*DIM;
    float s = 0.f, t = 0.f;
    #pragma unroll
    for (int d = lane; d < DIM; d += 32){
        float v = hr[d];
        s += v * g_va_src[h*DIM + d];
        t += v * g_va_dst[h*DIM + d];
    }
    #pragma unroll
    for (int o = 16; o > 0; o >>= 1){
        s += __shfl_down_sync(0xffffffffu, s, o);
        t += __shfl_down_sync(0xffffffffu, t, o);
    }
    if (lane == 0){ g_src[row*NH + h] = s; g_dst[row*NH + h] = t; }
}

__device__ __forceinline__ void compute_weights(int row, int b, int cnt,
                                                const int* nbr, float* w, float* srcI){
    int tid = threadIdx.x;
    if (tid < NH) srcI[tid] = g_src[row*NH + tid];
    __syncthreads();
    for (int idx = tid; idx < cnt*NH; idx += 256){
        int n = idx >> 3, h = idx & 7;
        float e = srcI[h] + g_dst[(size_t)(b*SEQ + nbr[n])*NH + h];
        w[n*NH + h] = e > 0.f ? e : 0.2f*e;
    }
    __syncthreads();
    int h = tid >> 5, lane = tid & 31;
    float m = -1e30f;
    for (int n = lane; n < cnt; n += 32) m = fmaxf(m, w[n*NH + h]);
    #pragma unroll
    for (int o = 16; o > 0; o >>= 1) m = fmaxf(m, __shfl_xor_sync(0xffffffffu, m, o));
    float ssum = 0.f;
    for (int n = lane; n < cnt; n += 32){
        float e = expf(w[n*NH + h] - m);
        w[n*NH + h] = e;
        ssum += e;
    }
    #pragma unroll
    for (int o = 16; o > 0; o >>= 1) ssum += __shfl_xor_sync(0xffffffffu, ssum, o);
    float inv = 1.f / ssum;
    for (int n = lane; n < cnt; n += 32) w[n*NH + h] *= inv;
    __syncthreads();
}

// aggregate + residual + ELU; writes fp32 h and bf16 split (for next GEMM's A)
__global__ __launch_bounds__(256)
void attn01(const float* __restrict__ resid, float* __restrict__ out){
    int row = blockIdx.x;
    int b = row / SEQ;
    int tid = threadIdx.x;
    int cnt = g_cnt[row];
    __shared__ int   nbr[MAXN];
    __shared__ float w[MAXN*NH];
    __shared__ float srcI[NH];
    for (int n = tid; n < cnt; n += 256) nbr[n] = g_nbr[row*MAXN + n];
    __syncthreads();
    compute_weights(row, b, cnt, nbr, w, srcI);
    int ch = tid;
    int hh = ch >> 5;
    float acc = 0.f;
    for (int n = 0; n < cnt; n++)
        acc += w[n*NH + hh] * g_hp[((size_t)(b*SEQ + nbr[n]))*DIM + ch];
    size_t oi = (size_t)row*DIM + ch;
    float v = acc + resid[oi];
    v = v > 0.f ? v : expm1f(v);
    out[oi] = v;
    split_val(v, gA_hi[oi], gA_lo[oi]);
}

// layer 2: aggregate h per head, write bf16 split at [row, h*256+c]
__global__ __launch_bounds__(256)
void attn2b(){
    int row = blockIdx.x;
    int b = row / SEQ;
    int tid = threadIdx.x;
    int cnt = g_cnt[row];
    __shared__ int   nbr[MAXN];
    __shared__ float w[MAXN*NH];
    __shared__ float srcI[NH];
    for (int n = tid; n < cnt; n += 256) nbr[n] = g_nbr[row*MAXN + n];
    __syncthreads();
    compute_weights(row, b, cnt, nbr, w, srcI);
    int c = tid;
    float acc[NH] = {};
    for (int n = 0; n < cnt; n++){
        float v = g_h[(size_t)(b*SEQ + nbr[n])*DIM + c];
        const float* wp = &w[n*NH];
        #pragma unroll
        for (int h = 0; h < NH; h++) acc[h] += wp[h]*v;
    }
    #pragma unroll
    for (int h = 0; h < NH; h++){
        size_t oi = (size_t)row*HD2 + h*DIM + c;
        split_val(acc[h], gA_hi[oi], gA_lo[oi]);
    }
}

// ---------------- LayerNorm (writes fp32 + split) -------------------------------
__global__ void layernorm(const float* __restrict__ in,
                          const float* __restrict__ ln_g, const float* __restrict__ ln_b,
                          float* __restrict__ out){
    int row = blockIdx.x, tid = threadIdx.x;
    float v = in[(size_t)row*DIM + tid];
    __shared__ float red[8];
    __shared__ float mu, rstd;
    float s = v;
    #pragma unroll
    for (int o = 16; o > 0; o >>= 1) s += __shfl_xor_sync(0xffffffffu, s, o);
    if ((tid & 31) == 0) red[tid >> 5] = s;
    __syncthreads();
    if (tid == 0){ float t = 0.f; for (int i = 0; i < 8; i++) t += red[i]; mu = t / 256.f; }
    __syncthreads();
    float d = v - mu;
    s = d*d;
    #pragma unroll
    for (int o = 16; o > 0; o >>= 1) s += __shfl_xor_sync(0xffffffffu, s, o);
    if ((tid & 31) == 0) red[tid >> 5] = s;
    __syncthreads();
    if (tid == 0){ float t = 0.f; for (int i = 0; i < 8; i++) t += red[i]; rstd = rsqrtf(t/256.f + 1e-5f); }
    __syncthreads();
    size_t oi = (size_t)row*DIM + tid;
    float o = d*rstd*ln_g[tid] + ln_b[tid];
    out[oi] = o;
    split_val(o, gA_hi[oi], gA_lo[oi]);
}

// ---------------- launch ---------------------------------------------------------
extern "C" void kernel_launch(void* const* d_in, const int* in_sizes, int n_in,
                              void* d_out, int out_size){
    const float* adj    = (const float*)d_in[0];
    const float* x      = (const float*)d_in[1];
    const float* W0     = (const float*)d_in[2];
    const float* a_src0 = (const float*)d_in[3];
    const float* a_dst0 = (const float*)d_in[4];
    const float* W1     = (const float*)d_in[5];
    const float* a_src1 = (const float*)d_in[6];
    const float* a_dst1 = (const float*)d_in[7];
    const float* W2     = (const float*)d_in[8];
    const float* a_src2 = (const float*)d_in[9];
    const float* a_dst2 = (const float*)d_in[10];
    const float* ln_g   = (const float*)d_in[11];
    const float* ln_b   = (const float*)d_in[12];
    const float* ff_w1  = (const float*)d_in[13];
    const float* ff_b1  = (const float*)d_in[14];
    const float* ff_w2  = (const float*)d_in[15];
    const float* ff_b2  = (const float*)d_in[16];
    float* out = (float*)d_out;

    float *p_hp, *p_h, *p_tmp, *p_ln;
    __nv_bfloat16 *pAh, *pAl, *pFh, *pFl;
    __nv_bfloat16 *pw0h,*pw0l,*pw1h,*pw1l,*pw2h,*pw2l,*pf1h,*pf1l,*pf2h,*pf2l;
    cudaGetSymbolAddress((void**)&p_hp,  g_hp);
    cudaGetSymbolAddress((void**)&p_h,   g_h);
    cudaGetSymbolAddress((void**)&p_tmp, g_tmp);
    cudaGetSymbolAddress((void**)&p_ln,  g_ln);
    cudaGetSymbolAddress((void**)&pAh, gA_hi);  cudaGetSymbolAddress((void**)&pAl, gA_lo);
    cudaGetSymbolAddress((void**)&pFh, gF_hi);  cudaGetSymbolAddress((void**)&pFl, gF_lo);
    cudaGetSymbolAddress((void**)&pw0h, w0_hi); cudaGetSymbolAddress((void**)&pw0l, w0_lo);
    cudaGetSymbolAddress((void**)&pw1h, w1_hi); cudaGetSymbolAddress((void**)&pw1l, w1_lo);
    cudaGetSymbolAddress((void**)&pw2h, w2_hi); cudaGetSymbolAddress((void**)&pw2l, w2_lo);
    cudaGetSymbolAddress((void**)&pf1h, f1_hi); cudaGetSymbolAddress((void**)&pf1l, f1_lo);
    cudaGetSymbolAddress((void**)&pf2h, f2_hi); cudaGetSymbolAddress((void**)&pf2l, f2_lo);

    // dynamic smem: TN=64 -> 61440 B, TN=128 -> 81920 B
    const int SM64  = 2*(2*128*40*2 + 2*64*40*2);
    const int SM128 = 2*(2*128*40*2 + 2*128*40*2);
    cudaFuncSetAttribute(gemm_mma<0,64>,  cudaFuncAttributeMaxDynamicSharedMemorySize, SM64);
    cudaFuncSetAttribute(gemm_mma<3,64>,  cudaFuncAttributeMaxDynamicSharedMemorySize, SM64);
    cudaFuncSetAttribute(gemm_mma<2,64>,  cudaFuncAttributeMaxDynamicSharedMemorySize, SM64);
    cudaFuncSetAttribute(gemm_mma<1,128>, cudaFuncAttributeMaxDynamicSharedMemorySize, SM128);

    dim3 blk(256);
    build_nbr<<<ROWS, blk>>>(adj);
    wsplit<<<DIM*DIM/256, blk>>>(W0, pw0h, pw0l, DIM, DIM, 1.f);
    wsplit<<<DIM*DIM/256, blk>>>(W1, pw1h, pw1l, DIM, DIM, 1.f);
    w2split<<<DIM*HD2/256, blk>>>(W2);
    wsplit<<<FFH*DIM/256, blk>>>(ff_w1, pf1h, pf1l, DIM, FFH, 1.f);
    wsplit<<<DIM*FFH/256, blk>>>(ff_w2, pf2h, pf2l, FFH, DIM, 1.f);
    va_compute<<<256, blk>>>(W2, a_src2, a_dst2);
    split_x<<<ROWS*DIM/256, blk>>>(x);

    // ---- GAT layer 0 ----
    gemm_mma<0,64><<<dim3(4,32), blk, SM64>>>(pAh, pAl, pw0h, pw0l, nullptr, nullptr,
                                              p_hp, nullptr, nullptr, ROWS, DIM, DIM);
    scores01<<<ROWS, blk>>>(a_src0, a_dst0);
    attn01<<<ROWS, blk>>>(x, p_h);

    // ---- GAT layer 1 ----
    gemm_mma<0,64><<<dim3(4,32), blk, SM64>>>(pAh, pAl, pw1h, pw1l, nullptr, nullptr,
                                              p_hp, nullptr, nullptr, ROWS, DIM, DIM);
    scores01<<<ROWS, blk>>>(a_src1, a_dst1);
    attn01<<<ROWS, blk>>>(p_h, p_h);

    // ---- GAT layer 2 (aggregate h per head, then permuted W2) ----
    scores2b<<<ROWS, blk>>>();
    attn2b<<<ROWS, blk>>>();
    gemm_mma<3,64><<<dim3(4,32), blk, SM64>>>(pAh, pAl, pw2h, pw2l, nullptr, p_h,
                                              p_tmp, nullptr, nullptr, ROWS, DIM, HD2);

    // ---- LayerNorm ----
    layernorm<<<ROWS, blk>>>(p_tmp, ln_g, ln_b, p_ln);

    // ---- FFN ----
    gemm_mma<1,128><<<dim3(4,32), blk, SM128>>>(pAh, pAl, pf1h, pf1l, ff_b1, nullptr,
                                                nullptr, pFh, pFl, ROWS, FFH, DIM);
    gemm_mma<2,64><<<dim3(4,32), blk, SM64>>>(pFh, pFl, pf2h, pf2l, ff_b2, p_ln,
                                              out, nullptr, nullptr, ROWS, DIM, FFH);
}

// round 5
// speedup vs baseline: 2.0505x; 1.0986x over previous
#include <cuda_runtime.h>
#include <cuda_bf16.h>
#include <math.h>
#include <stdint.h>

#define BATCH 4
#define SEQ 1024
#define DIM 256
#define NH 8
#define DH 32
#define ROWS (BATCH*SEQ)      // 4096
#define MAXN 256
#define FFH 512
#define HD2 (NH*DIM)          // 2048

// ---------------- scratch (static device globals; no allocation) ----------------
__device__ float g_hp [ROWS*DIM];
__device__ float g_h  [ROWS*DIM];
__device__ float g_tmp[ROWS*DIM];
__device__ float g_ln [ROWS*DIM];
__device__ __nv_bfloat16 gA_hi[ROWS*HD2];
__device__ __nv_bfloat16 gA_lo[ROWS*HD2];
__device__ __nv_bfloat16 gF_hi[ROWS*FFH];
__device__ __nv_bfloat16 gF_lo[ROWS*FFH];
__device__ __nv_bfloat16 w0_hi[DIM*DIM],  w0_lo[DIM*DIM];
__device__ __nv_bfloat16 w1_hi[DIM*DIM],  w1_lo[DIM*DIM];
__device__ __nv_bfloat16 w2_hi[DIM*HD2],  w2_lo[DIM*HD2];
__device__ __nv_bfloat16 f1_hi[FFH*DIM],  f1_lo[FFH*DIM];
__device__ __nv_bfloat16 f2_hi[DIM*FFH],  f2_lo[DIM*FFH];
__device__ float g_va_src[NH*DIM];
__device__ float g_va_dst[NH*DIM];
__device__ float g_src[ROWS*NH];
__device__ float g_dst[ROWS*NH];
__device__ int   g_nbr[ROWS*MAXN];
__device__ int   g_cnt[ROWS];

// ---------------- helpers ---------------------------------------------------------
__device__ __forceinline__ uint32_t smem_u32(const void* p){
    uint32_t a;
    asm("{ .reg .u64 t; cvta.to.shared.u64 t, %1; cvt.u32.u64 %0, t; }" : "=r"(a) : "l"(p));
    return a;
}
__device__ __forceinline__ void split_val(float v, __nv_bfloat16& hi, __nv_bfloat16& lo){
    hi = __float2bfloat16(v);
    lo = __float2bfloat16(v - __bfloat162float(hi));
}
#define CPA16(dst, src) \
    asm volatile("cp.async.cg.shared.global [%0], [%1], 16;" :: "r"(dst), "l"(src) : "memory")
#define LDSM4(r0,r1,r2,r3,addr) \
    asm volatile("ldmatrix.sync.aligned.m8n8.x4.shared.b16 {%0,%1,%2,%3}, [%4];" \
        : "=r"(r0),"=r"(r1),"=r"(r2),"=r"(r3) : "r"(addr))

__device__ __forceinline__ void mma_bf16(float* c, const uint32_t* a, uint32_t b0, uint32_t b1){
    asm volatile("mma.sync.aligned.m16n8k16.row.col.f32.bf16.bf16.f32 "
        "{%0,%1,%2,%3}, {%4,%5,%6,%7}, {%8,%9}, {%0,%1,%2,%3};"
        : "+f"(c[0]),"+f"(c[1]),"+f"(c[2]),"+f"(c[3])
        : "r"(a[0]),"r"(a[1]),"r"(a[2]),"r"(a[3]), "r"(b0),"r"(b1));
}

// ---------------- HMMA split-bf16 GEMM: C[M,N] = A[M,K] @ Bt[N,K]^T ---------------
// EPI: 0 plain fp32; 1 +bias,GELU -> bf16 hi/lo; 2 +bias+res fp32; 3 +res fp32
template<int EPI, int TN>
__global__ __launch_bounds__(256)
void gemm_mma(const __nv_bfloat16* __restrict__ Ah, const __nv_bfloat16* __restrict__ Al,
              const __nv_bfloat16* __restrict__ Bh, const __nv_bfloat16* __restrict__ Bl,
              const float* __restrict__ bias, const float* __restrict__ res,
              float* __restrict__ C, __nv_bfloat16* __restrict__ Chi, __nv_bfloat16* __restrict__ Clo,
              int M, int N, int K){
    constexpr int LD   = 40;
    constexpr int A_SZ = 128*LD*2;
    constexpr int B_SZ = TN*LD*2;
    constexpr int BUF  = 2*A_SZ + 2*B_SZ;
    constexpr int NB   = TN/16;
    constexpr int NP   = TN/32;
    extern __shared__ char sm[];
    uint32_t sb = smem_u32(sm);
    int tid = threadIdx.x, lane = tid & 31, wid = tid >> 5;
    int bm = blockIdx.y*128, bn = blockIdx.x*TN;
    int wm = (wid & 3)*32, wn = (wid >> 2)*(TN/2);
    float acc[2][NB][4] = {};
    int nch = K >> 5;

    auto load_chunk = [&](int c, int b){
        uint32_t s0 = sb + b*BUF;
        int k0 = c*32;
        #pragma unroll
        for (int i = 0; i < 2; i++){
            int u = tid + i*256;
            int row = u >> 2, c8 = u & 3;
            uint32_t so = (uint32_t)(row*LD + c8*8)*2;
            size_t go = (size_t)(bm + row)*K + k0 + c8*8;
            CPA16(s0 + so,        Ah + go);
            CPA16(s0 + A_SZ + so, Al + go);
        }
        for (int u = tid; u < TN*4; u += 256){
            int row = u >> 2, c8 = u & 3;
            uint32_t so = (uint32_t)(row*LD + c8*8)*2;
            size_t go = (size_t)(bn + row)*K + k0 + c8*8;
            CPA16(s0 + 2*A_SZ + so,        Bh + go);
            CPA16(s0 + 2*A_SZ + B_SZ + so, Bl + go);
        }
        asm volatile("cp.async.commit_group;" ::: "memory");
    };

    load_chunk(0, 0);
    for (int c = 0; c < nch; c++){
        if (c + 1 < nch){
            load_chunk(c + 1, (c + 1) & 1);
            asm volatile("cp.async.wait_group 1;" ::: "memory");
        } else {
            asm volatile("cp.async.wait_group 0;" ::: "memory");
        }
        __syncthreads();
        uint32_t sA = sb + (c & 1)*BUF;
        uint32_t sB = sA + 2*A_SZ;
        #pragma unroll
        for (int kk = 0; kk < 32; kk += 16){
            uint32_t ah[2][4], al[2][4];
            #pragma unroll
            for (int mb = 0; mb < 2; mb++){
                uint32_t ad = sA + (uint32_t)(((wm + mb*16 + (lane & 15))*LD + kk + (lane >> 4)*8)*2);
                LDSM4(ah[mb][0],ah[mb][1],ah[mb][2],ah[mb][3], ad);
                LDSM4(al[mb][0],al[mb][1],al[mb][2],al[mb][3], ad + A_SZ);
            }
            #pragma unroll
            for (int p = 0; p < NP; p++){
                uint32_t bd = sB + (uint32_t)(((wn + p*16 + ((lane >> 4) << 3) + (lane & 7))*LD
                                              + kk + ((lane >> 3) & 1)*8)*2);
                uint32_t bh[4], bl[4];
                LDSM4(bh[0],bh[1],bh[2],bh[3], bd);
                LDSM4(bl[0],bl[1],bl[2],bl[3], bd + B_SZ);
                #pragma unroll
                for (int mb = 0; mb < 2; mb++){
                    #pragma unroll
                    for (int j = 0; j < 2; j++){
                        float* a_ = acc[mb][p*2 + j];
                        mma_bf16(a_, ah[mb], bh[2*j], bh[2*j+1]);
                        mma_bf16(a_, ah[mb], bl[2*j], bl[2*j+1]);
                        mma_bf16(a_, al[mb], bh[2*j], bh[2*j+1]);
                    }
                }
            }
        }
        __syncthreads();
    }

    // epilogue (paired stores)
    int g = lane >> 2, tg = lane & 3;
    #pragma unroll
    for (int mb = 0; mb < 2; mb++){
        #pragma unroll
        for (int nb = 0; nb < NB; nb++){
            float* a_ = acc[mb][nb];
            int col = bn + wn + nb*8 + tg*2;
            #pragma unroll
            for (int half = 0; half < 2; half++){
                int r = bm + wm + mb*16 + g + half*8;
                size_t ci = (size_t)r*N + col;
                float v0 = a_[half*2], v1 = a_[half*2+1];
                if (EPI == 0){
                    *(float2*)&C[ci] = make_float2(v0, v1);
                } else if (EPI == 1){
                    v0 += bias[col]; v1 += bias[col+1];
                    float t0 = 0.7978845608028654f*(v0 + 0.044715f*v0*v0*v0);
                    v0 = 0.5f*v0*(1.f + tanhf(t0));
                    float t1 = 0.7978845608028654f*(v1 + 0.044715f*v1*v1*v1);
                    v1 = 0.5f*v1*(1.f + tanhf(t1));
                    __nv_bfloat16 h0,l0,h1,l1;
                    split_val(v0,h0,l0); split_val(v1,h1,l1);
                    __nv_bfloat162 hp2; hp2.x=h0; hp2.y=h1;
                    __nv_bfloat162 lp2; lp2.x=l0; lp2.y=l1;
                    *(__nv_bfloat162*)&Chi[ci] = hp2;
                    *(__nv_bfloat162*)&Clo[ci] = lp2;
                } else if (EPI == 2){
                    float2 rr = *(const float2*)&res[ci];
                    *(float2*)&C[ci] = make_float2(v0 + bias[col] + rr.x, v1 + bias[col+1] + rr.y);
                } else {
                    float2 rr = *(const float2*)&res[ci];
                    *(float2*)&C[ci] = make_float2(v0 + rr.x, v1 + rr.y);
                }
            }
        }
    }
}

// ---------------- neighbor list build: one warp per row --------------------------
__global__ __launch_bounds__(256)
void build_nbr(const float* __restrict__ adj){
    int row = (blockIdx.x*256 + threadIdx.x) >> 5;
    int lane = threadIdx.x & 31;
    if (row >= ROWS) return;
    const float* arow = adj + (size_t)row * SEQ;
    int cnt = 0;
    for (int base = 0; base < SEQ; base += 128){
        float v0 = arow[base + lane];
        float v1 = arow[base + 32 + lane];
        float v2 = arow[base + 64 + lane];
        float v3 = arow[base + 96 + lane];
        float vv[4] = {v0, v1, v2, v3};
        #pragma unroll
        for (int i = 0; i < 4; i++){
            bool p = vv[i] > 0.f;
            unsigned m = __ballot_sync(0xffffffffu, p);
            if (p){
                int pos = cnt + __popc(m & ((1u << lane) - 1u));
                if (pos < MAXN) g_nbr[row*MAXN + pos] = base + i*32 + lane;
            }
            cnt += __popc(m);
        }
    }
    if (lane == 0) g_cnt[row] = cnt < MAXN ? cnt : MAXN;
}

// ---------------- merged prep: transposes + split_x + va --------------------------
// block ranges: [0,64) w0 | [64,128) w1 | [128,640) w2 | [640,768) f1 | [768,896) f2
//               [896,4992) split_x | [4992,5248) va
__device__ __forceinline__ void trans_tile(const float* __restrict__ inp, int ldi,
                                           __nv_bfloat16* __restrict__ oh, __nv_bfloat16* __restrict__ ol,
                                           int ldo, int kt, int nt, float scale){
    __shared__ float tile[32][33];
    int tx = threadIdx.x & 31, ty0 = threadIdx.x >> 5;
    #pragma unroll
    for (int i = 0; i < 4; i++){
        int ty = ty0 + i*8;
        tile[ty][tx] = inp[(size_t)(kt*32 + ty)*ldi + nt*32 + tx];
    }
    __syncthreads();
    #pragma unroll
    for (int i = 0; i < 4; i++){
        int ty = ty0 + i*8;                       // local n
        float v = scale * tile[tx][ty];           // [k_local=tx][n_local=ty]
        size_t oi = (size_t)(nt*32 + ty)*ldo + kt*32 + tx;
        __nv_bfloat16 hi, lo; split_val(v, hi, lo);
        oh[oi] = hi; ol[oi] = lo;
    }
}

__global__ __launch_bounds__(256)
void prep(const float* __restrict__ W0, const float* __restrict__ W1, const float* __restrict__ W2,
          const float* __restrict__ F1, const float* __restrict__ F2,
          const float* __restrict__ x,
          const float* __restrict__ as2, const float* __restrict__ ad2){
    int b = blockIdx.x, tid = threadIdx.x;
    if (b < 64){
        trans_tile(W0, DIM, w0_hi, w0_lo, DIM, b >> 3, b & 7, 1.f);
    } else if (b < 128){
        int t = b - 64;
        trans_tile(W1, DIM, w1_hi, w1_lo, DIM, t >> 3, t & 7, 1.f);
    } else if (b < 640){
        int rel = b - 128, h = rel >> 6, t = rel & 63;
        trans_tile(W2 + h*DIM, HD2, w2_hi + h*DIM, w2_lo + h*DIM, HD2, t >> 3, t & 7, 0.125f);
    } else if (b < 768){
        int rel = b - 640;               // K=256 (8 kt), N=512 (16 nt)
        trans_tile(F1, FFH, f1_hi, f1_lo, DIM, rel >> 4, rel & 15, 1.f);
    } else if (b < 896){
        int rel = b - 768;               // K=512 (16 kt), N=256 (8 nt)
        trans_tile(F2, DIM, f2_hi, f2_lo, FFH, rel >> 3, rel & 7, 1.f);
    } else if (b < 4992){
        int idx = (b - 896)*256 + tid;
        split_val(x[idx], gA_hi[idx], gA_lo[idx]);
    } else {
        int rel = b - 4992;
        int gw = rel*8 + (tid >> 5);
        int lane = tid & 31;
        int h = gw >> 8, c = gw & 255;
        float s = 0.f, t = 0.f;
        #pragma unroll
        for (int d = lane; d < DIM; d += 32){
            float wv = W2[(size_t)c*HD2 + h*DIM + d];
            s += wv * as2[h*DIM + d];
            t += wv * ad2[h*DIM + d];
        }
        #pragma unroll
        for (int o = 16; o > 0; o >>= 1){
            s += __shfl_down_sync(0xffffffffu, s, o);
            t += __shfl_down_sync(0xffffffffu, t, o);
        }
        if (lane == 0){ g_va_src[h*DIM + c] = s; g_va_dst[h*DIM + c] = t; }
    }
}

// ---------------- attention scores ----------------------------------------------
__global__ void scores01(const float* __restrict__ a_src, const float* __restrict__ a_dst){
    int row = blockIdx.x;
    int tid = threadIdx.x;
    int h = tid >> 5, d = tid & 31;
    float v = g_hp[(size_t)row*DIM + h*DH + d];
    float s = v * a_src[h*DH + d];
    float t = v * a_dst[h*DH + d];
    #pragma unroll
    for (int o = 16; o > 0; o >>= 1){
        s += __shfl_down_sync(0xffffffffu, s, o);
        t += __shfl_down_sync(0xffffffffu, t, o);
    }
    if (d == 0){ g_src[row*NH + h] = s; g_dst[row*NH + h] = t; }
}
__global__ void scores2b(){
    int row = blockIdx.x;
    int h = threadIdx.x >> 5, lane = threadIdx.x & 31;
    const float* hr = g_h + (size_t)row*DIM;
    float s = 0.f, t = 0.f;
    #pragma unroll
    for (int d = lane; d < DIM; d += 32){
        float v = hr[d];
        s += v * g_va_src[h*DIM + d];
        t += v * g_va_dst[h*DIM + d];
    }
    #pragma unroll
    for (int o = 16; o > 0; o >>= 1){
        s += __shfl_down_sync(0xffffffffu, s, o);
        t += __shfl_down_sync(0xffffffffu, t, o);
    }
    if (lane == 0){ g_src[row*NH + h] = s; g_dst[row*NH + h] = t; }
}

__device__ __forceinline__ void compute_weights(int row, int b, int cnt,
                                                const int* nbr, float* w, float* srcI){
    int tid = threadIdx.x;
    if (tid < NH) srcI[tid] = g_src[row*NH + tid];
    __syncthreads();
    for (int idx = tid; idx < cnt*NH; idx += 256){
        int n = idx >> 3, h = idx & 7;
        float e = srcI[h] + g_dst[(size_t)(b*SEQ + nbr[n])*NH + h];
        w[n*NH + h] = e > 0.f ? e : 0.2f*e;
    }
    __syncthreads();
    int h = tid >> 5, lane = tid & 31;
    float m = -1e30f;
    for (int n = lane; n < cnt; n += 32) m = fmaxf(m, w[n*NH + h]);
    #pragma unroll
    for (int o = 16; o > 0; o >>= 1) m = fmaxf(m, __shfl_xor_sync(0xffffffffu, m, o));
    float ssum = 0.f;
    for (int n = lane; n < cnt; n += 32){
        float e = expf(w[n*NH + h] - m);
        w[n*NH + h] = e;
        ssum += e;
    }
    #pragma unroll
    for (int o = 16; o > 0; o >>= 1) ssum += __shfl_xor_sync(0xffffffffu, ssum, o);
    float inv = 1.f / ssum;
    for (int n = lane; n < cnt; n += 32) w[n*NH + h] *= inv;
    __syncthreads();
}

// aggregate + residual + ELU; writes fp32 h and bf16 split
__global__ __launch_bounds__(256)
void attn01(const float* __restrict__ resid, float* __restrict__ out){
    int row = blockIdx.x;
    int b = row / SEQ;
    int tid = threadIdx.x;
    int cnt = g_cnt[row];
    __shared__ int   nbr[MAXN];
    __shared__ float w[MAXN*NH];
    __shared__ float srcI[NH];
    for (int n = tid; n < cnt; n += 256) nbr[n] = g_nbr[row*MAXN + n];
    __syncthreads();
    compute_weights(row, b, cnt, nbr, w, srcI);
    int ch = tid;
    int hh = ch >> 5;
    float acc = 0.f;
    int n = 0;
    for (; n + 4 <= cnt; n += 4){
        int j0 = nbr[n], j1 = nbr[n+1], j2 = nbr[n+2], j3 = nbr[n+3];
        float v0 = g_hp[((size_t)(b*SEQ + j0))*DIM + ch];
        float v1 = g_hp[((size_t)(b*SEQ + j1))*DIM + ch];
        float v2 = g_hp[((size_t)(b*SEQ + j2))*DIM + ch];
        float v3 = g_hp[((size_t)(b*SEQ + j3))*DIM + ch];
        acc = fmaf(w[(n+0)*NH + hh], v0, acc);
        acc = fmaf(w[(n+1)*NH + hh], v1, acc);
        acc = fmaf(w[(n+2)*NH + hh], v2, acc);
        acc = fmaf(w[(n+3)*NH + hh], v3, acc);
    }
    for (; n < cnt; n++)
        acc = fmaf(w[n*NH + hh], g_hp[((size_t)(b*SEQ + nbr[n]))*DIM + ch], acc);
    size_t oi = (size_t)row*DIM + ch;
    float v = acc + resid[oi];
    v = v > 0.f ? v : expm1f(v);
    out[oi] = v;
    split_val(v, gA_hi[oi], gA_lo[oi]);
}

// layer 2: aggregate h per head, write bf16 split at [row, h*256+c]
__global__ __launch_bounds__(256)
void attn2b(){
    int row = blockIdx.x;
    int b = row / SEQ;
    int tid = threadIdx.x;
    int cnt = g_cnt[row];
    __shared__ int   nbr[MAXN];
    __shared__ float w[MAXN*NH];
    __shared__ float srcI[NH];
    for (int n = tid; n < cnt; n += 256) nbr[n] = g_nbr[row*MAXN + n];
    __syncthreads();
    compute_weights(row, b, cnt, nbr, w, srcI);
    int c = tid;
    float acc[NH] = {};
    int n = 0;
    for (; n + 2 <= cnt; n += 2){
        int j0 = nbr[n], j1 = nbr[n+1];
        float v0 = g_h[(size_t)(b*SEQ + j0)*DIM + c];
        float v1 = g_h[(size_t)(b*SEQ + j1)*DIM + c];
        const float* w0p = &w[n*NH];
        const float* w1p = &w[(n+1)*NH];
        #pragma unroll
        for (int h = 0; h < NH; h++){
            acc[h] = fmaf(w0p[h], v0, acc[h]);
            acc[h] = fmaf(w1p[h], v1, acc[h]);
        }
    }
    for (; n < cnt; n++){
        float v = g_h[(size_t)(b*SEQ + nbr[n])*DIM + c];
        const float* wp = &w[n*NH];
        #pragma unroll
        for (int h = 0; h < NH; h++) acc[h] = fmaf(wp[h], v, acc[h]);
    }
    #pragma unroll
    for (int h = 0; h < NH; h++){
        size_t oi = (size_t)row*HD2 + h*DIM + c;
        split_val(acc[h], gA_hi[oi], gA_lo[oi]);
    }
}

// ---------------- LayerNorm (writes fp32 + split) -------------------------------
__global__ void layernorm(const float* __restrict__ in,
                          const float* __restrict__ ln_g, const float* __restrict__ ln_b,
                          float* __restrict__ out){
    int row = blockIdx.x, tid = threadIdx.x;
    float v = in[(size_t)row*DIM + tid];
    __shared__ float red[8];
    __shared__ float mu, rstd;
    float s = v;
    #pragma unroll
    for (int o = 16; o > 0; o >>= 1) s += __shfl_xor_sync(0xffffffffu, s, o);
    if ((tid & 31) == 0) red[tid >> 5] = s;
    __syncthreads();
    if (tid == 0){ float t = 0.f; for (int i = 0; i < 8; i++) t += red[i]; mu = t / 256.f; }
    __syncthreads();
    float d = v - mu;
    s = d*d;
    #pragma unroll
    for (int o = 16; o > 0; o >>= 1) s += __shfl_xor_sync(0xffffffffu, s, o);
    if ((tid & 31) == 0) red[tid >> 5] = s;
    __syncthreads();
    if (tid == 0){ float t = 0.f; for (int i = 0; i < 8; i++) t += red[i]; rstd = rsqrtf(t/256.f + 1e-5f); }
    __syncthreads();
    size_t oi = (size_t)row*DIM + tid;
    float o = d*rstd*ln_g[tid] + ln_b[tid];
    out[oi] = o;
    split_val(o, gA_hi[oi], gA_lo[oi]);
}

// ---------------- launch ---------------------------------------------------------
extern "C" void kernel_launch(void* const* d_in, const int* in_sizes, int n_in,
                              void* d_out, int out_size){
    const float* adj    = (const float*)d_in[0];
    const float* x      = (const float*)d_in[1];
    const float* W0     = (const float*)d_in[2];
    const float* a_src0 = (const float*)d_in[3];
    const float* a_dst0 = (const float*)d_in[4];
    const float* W1     = (const float*)d_in[5];
    const float* a_src1 = (const float*)d_in[6];
    const float* a_dst1 = (const float*)d_in[7];
    const float* W2     = (const float*)d_in[8];
    const float* a_src2 = (const float*)d_in[9];
    const float* a_dst2 = (const float*)d_in[10];
    const float* ln_g   = (const float*)d_in[11];
    const float* ln_b   = (const float*)d_in[12];
    const float* ff_w1  = (const float*)d_in[13];
    const float* ff_b1  = (const float*)d_in[14];
    const float* ff_w2  = (const float*)d_in[15];
    const float* ff_b2  = (const float*)d_in[16];
    float* out = (float*)d_out;

    float *p_hp, *p_h, *p_tmp, *p_ln;
    __nv_bfloat16 *pAh, *pAl, *pFh, *pFl;
    __nv_bfloat16 *pw0h,*pw0l,*pw1h,*pw1l,*pw2h,*pw2l,*pf1h,*pf1l,*pf2h,*pf2l;
    cudaGetSymbolAddress((void**)&p_hp,  g_hp);
    cudaGetSymbolAddress((void**)&p_h,   g_h);
    cudaGetSymbolAddress((void**)&p_tmp, g_tmp);
    cudaGetSymbolAddress((void**)&p_ln,  g_ln);
    cudaGetSymbolAddress((void**)&pAh, gA_hi);  cudaGetSymbolAddress((void**)&pAl, gA_lo);
    cudaGetSymbolAddress((void**)&pFh, gF_hi);  cudaGetSymbolAddress((void**)&pFl, gF_lo);
    cudaGetSymbolAddress((void**)&pw0h, w0_hi); cudaGetSymbolAddress((void**)&pw0l, w0_lo);
    cudaGetSymbolAddress((void**)&pw1h, w1_hi); cudaGetSymbolAddress((void**)&pw1l, w1_lo);
    cudaGetSymbolAddress((void**)&pw2h, w2_hi); cudaGetSymbolAddress((void**)&pw2l, w2_lo);
    cudaGetSymbolAddress((void**)&pf1h, f1_hi); cudaGetSymbolAddress((void**)&pf1l, f1_lo);
    cudaGetSymbolAddress((void**)&pf2h, f2_hi); cudaGetSymbolAddress((void**)&pf2l, f2_lo);

    const int SM64  = 2*(2*128*40*2 + 2*64*40*2);
    const int SM128 = 2*(2*128*40*2 + 2*128*40*2);
    cudaFuncSetAttribute(gemm_mma<0,64>,  cudaFuncAttributeMaxDynamicSharedMemorySize, SM64);
    cudaFuncSetAttribute(gemm_mma<3,64>,  cudaFuncAttributeMaxDynamicSharedMemorySize, SM64);
    cudaFuncSetAttribute(gemm_mma<2,64>,  cudaFuncAttributeMaxDynamicSharedMemorySize, SM64);
    cudaFuncSetAttribute(gemm_mma<1,128>, cudaFuncAttributeMaxDynamicSharedMemorySize, SM128);

    dim3 blk(256);
    build_nbr<<<ROWS/8, blk>>>(adj);
    prep<<<5248, blk>>>(W0, W1, W2, ff_w1, ff_w2, x, a_src2, a_dst2);

    // ---- GAT layer 0 ----
    gemm_mma<0,64><<<dim3(4,32), blk, SM64>>>(pAh, pAl, pw0h, pw0l, nullptr, nullptr,
                                              p_hp, nullptr, nullptr, ROWS, DIM, DIM);
    scores01<<<ROWS, blk>>>(a_src0, a_dst0);
    attn01<<<ROWS, blk>>>(x, p_h);

    // ---- GAT layer 1 ----
    gemm_mma<0,64><<<dim3(4,32), blk, SM64>>>(pAh, pAl, pw1h, pw1l, nullptr, nullptr,
                                              p_hp, nullptr, nullptr, ROWS, DIM, DIM);
    scores01<<<ROWS, blk>>>(a_src1, a_dst1);
    attn01<<<ROWS, blk>>>(p_h, p_h);

    // ---- GAT layer 2 ----
    scores2b<<<ROWS, blk>>>();
    attn2b<<<ROWS, blk>>>();
    gemm_mma<3,64><<<dim3(4,32), blk, SM64>>>(pAh, pAl, pw2h, pw2l, nullptr, p_h,
                                              p_tmp, nullptr, nullptr, ROWS, DIM, HD2);

    // ---- LayerNorm ----
    layernorm<<<ROWS, blk>>>(p_tmp, ln_g, ln_b, p_ln);

    // ---- FFN ----
    gemm_mma<1,128><<<dim3(4,32), blk, SM128>>>(pAh, pAl, pf1h, pf1l, ff_b1, nullptr,
                                                nullptr, pFh, pFl, ROWS, FFH, DIM);
    gemm_mma<2,64><<<dim3(4,32), blk, SM64>>>(pFh, pFl, pf2h, pf2l, ff_b2, p_ln,
                                              out, nullptr, nullptr, ROWS, DIM, FFH);
}

// round 6
// speedup vs baseline: 2.1360x; 1.0417x over previous
#include <cuda_runtime.h>
#include <cuda_bf16.h>
#include <math.h>
#include <stdint.h>

#define BATCH 4
#define SEQ 1024
#define DIM 256
#define NH 8
#define DH 32
#define ROWS (BATCH*SEQ)      // 4096
#define MAXN 256
#define FFH 512
#define HD2 (NH*DIM)          // 2048

// ---------------- scratch ---------------------------------------------------------
__device__ float g_hp [ROWS*DIM];
__device__ float g_h  [ROWS*DIM];
__device__ float g_tmp[ROWS*DIM];
__device__ float g_ln [ROWS*DIM];
__device__ __nv_bfloat16 gA_hi[ROWS*HD2];
__device__ __nv_bfloat16 gA_lo[ROWS*HD2];
__device__ __nv_bfloat16 gF_hi[ROWS*FFH];
__device__ __nv_bfloat16 gF_lo[ROWS*FFH];
__device__ __nv_bfloat16 w0_hi[DIM*DIM],  w0_lo[DIM*DIM];
__device__ __nv_bfloat16 w1_hi[DIM*DIM],  w1_lo[DIM*DIM];
__device__ __nv_bfloat16 w2_hi[DIM*HD2],  w2_lo[DIM*HD2];
__device__ __nv_bfloat16 f1_hi[FFH*DIM],  f1_lo[FFH*DIM];
__device__ __nv_bfloat16 f2_hi[DIM*FFH],  f2_lo[DIM*FFH];
__device__ float g_va_src[NH*DIM];
__device__ float g_va_dst[NH*DIM];
__device__ float g_src [ROWS*NH];
__device__ float g_dst [ROWS*NH];
__device__ float g_src2[ROWS*NH];
__device__ float g_dst2[ROWS*NH];
__device__ int   g_nbr[ROWS*MAXN];
__device__ int   g_cnt[ROWS];

// ---------------- helpers ---------------------------------------------------------
__device__ __forceinline__ uint32_t smem_u32(const void* p){
    uint32_t a;
    asm("{ .reg .u64 t; cvta.to.shared.u64 t, %1; cvt.u32.u64 %0, t; }" : "=r"(a) : "l"(p));
    return a;
}
__device__ __forceinline__ void split_val(float v, __nv_bfloat16& hi, __nv_bfloat16& lo){
    hi = __float2bfloat16(v);
    lo = __float2bfloat16(v - __bfloat162float(hi));
}
#define CPA16(dst, src) \
    asm volatile("cp.async.cg.shared.global [%0], [%1], 16;" :: "r"(dst), "l"(src) : "memory")
#define LDSM4(r0,r1,r2,r3,addr) \
    asm volatile("ldmatrix.sync.aligned.m8n8.x4.shared.b16 {%0,%1,%2,%3}, [%4];" \
        : "=r"(r0),"=r"(r1),"=r"(r2),"=r"(r3) : "r"(addr))

__device__ __forceinline__ void mma_bf16(float* c, const uint32_t* a, uint32_t b0, uint32_t b1){
    asm volatile("mma.sync.aligned.m16n8k16.row.col.f32.bf16.bf16.f32 "
        "{%0,%1,%2,%3}, {%4,%5,%6,%7}, {%8,%9}, {%0,%1,%2,%3};"
        : "+f"(c[0]),"+f"(c[1]),"+f"(c[2]),"+f"(c[3])
        : "r"(a[0]),"r"(a[1]),"r"(a[2]),"r"(a[3]), "r"(b0),"r"(b1));
}

// ---------------- HMMA split-bf16 GEMM, 3-stage pipeline --------------------------
// EPI: 0 plain; 1 +bias GELU -> bf16 split; 2 +bias+res; 3 +res; 4 plain + fused head scores
template<int EPI, int TN>
__global__ __launch_bounds__(256)
void gemm_mma(const __nv_bfloat16* __restrict__ Ah, const __nv_bfloat16* __restrict__ Al,
              const __nv_bfloat16* __restrict__ Bh, const __nv_bfloat16* __restrict__ Bl,
              const float* __restrict__ bias, const float* __restrict__ res,
              const float* __restrict__ asv, const float* __restrict__ adv,
              float* __restrict__ C, __nv_bfloat16* __restrict__ Chi, __nv_bfloat16* __restrict__ Clo,
              int M, int N, int K){
    constexpr int LD   = 40;
    constexpr int A_SZ = 128*LD*2;
    constexpr int B_SZ = TN*LD*2;
    constexpr int BUF  = 2*A_SZ + 2*B_SZ;
    constexpr int NB   = TN/16;
    constexpr int NP   = TN/32;
    extern __shared__ char sm[];
    uint32_t sb = smem_u32(sm);
    int tid = threadIdx.x, lane = tid & 31, wid = tid >> 5;
    int bm = blockIdx.y*128, bn = blockIdx.x*TN;
    int wm = (wid & 3)*32, wn = (wid >> 2)*(TN/2);
    float acc[2][NB][4] = {};
    int nch = K >> 5;

    auto load_chunk = [&](int c){
        uint32_t s0 = sb + (c % 3)*BUF;
        int k0 = c*32;
        #pragma unroll
        for (int i = 0; i < 2; i++){
            int u = tid + i*256;
            int row = u >> 2, c8 = u & 3;
            uint32_t so = (uint32_t)(row*LD + c8*8)*2;
            size_t go = (size_t)(bm + row)*K + k0 + c8*8;
            CPA16(s0 + so,        Ah + go);
            CPA16(s0 + A_SZ + so, Al + go);
        }
        for (int u = tid; u < TN*4; u += 256){
            int row = u >> 2, c8 = u & 3;
            uint32_t so = (uint32_t)(row*LD + c8*8)*2;
            size_t go = (size_t)(bn + row)*K + k0 + c8*8;
            CPA16(s0 + 2*A_SZ + so,        Bh + go);
            CPA16(s0 + 2*A_SZ + B_SZ + so, Bl + go);
        }
        asm volatile("cp.async.commit_group;" ::: "memory");
    };

    load_chunk(0);
    load_chunk(1);
    for (int c = 0; c < nch; c++){
        if (c + 2 < nch){
            load_chunk(c + 2);
            asm volatile("cp.async.wait_group 2;" ::: "memory");
        } else if (c + 1 < nch){
            asm volatile("cp.async.wait_group 1;" ::: "memory");
        } else {
            asm volatile("cp.async.wait_group 0;" ::: "memory");
        }
        __syncthreads();
        uint32_t sA = sb + (c % 3)*BUF;
        uint32_t sB = sA + 2*A_SZ;
        #pragma unroll
        for (int kk = 0; kk < 32; kk += 16){
            uint32_t ah[2][4], al[2][4];
            #pragma unroll
            for (int mb = 0; mb < 2; mb++){
                uint32_t ad = sA + (uint32_t)(((wm + mb*16 + (lane & 15))*LD + kk + (lane >> 4)*8)*2);
                LDSM4(ah[mb][0],ah[mb][1],ah[mb][2],ah[mb][3], ad);
                LDSM4(al[mb][0],al[mb][1],al[mb][2],al[mb][3], ad + A_SZ);
            }
            #pragma unroll
            for (int p = 0; p < NP; p++){
                uint32_t bd = sB + (uint32_t)(((wn + p*16 + ((lane >> 4) << 3) + (lane & 7))*LD
                                              + kk + ((lane >> 3) & 1)*8)*2);
                uint32_t bh[4], bl[4];
                LDSM4(bh[0],bh[1],bh[2],bh[3], bd);
                LDSM4(bl[0],bl[1],bl[2],bl[3], bd + B_SZ);
                #pragma unroll
                for (int mb = 0; mb < 2; mb++){
                    #pragma unroll
                    for (int j = 0; j < 2; j++){
                        float* a_ = acc[mb][p*2 + j];
                        mma_bf16(a_, ah[mb], bh[2*j], bh[2*j+1]);
                        mma_bf16(a_, ah[mb], bl[2*j], bl[2*j+1]);
                        mma_bf16(a_, al[mb], bh[2*j], bh[2*j+1]);
                    }
                }
            }
        }
        __syncthreads();
    }

    // epilogue
    int g = lane >> 2, tg = lane & 3;
    float ca[8], cd[8];
    float sacc[2][2] = {}, dacc[2][2] = {};
    int hidx = 0;
    if (EPI == 4){
        hidx = (bn + wn) >> 5;        // TN=64: warp tile = exactly one head
        #pragma unroll
        for (int nb = 0; nb < 4; nb++)
            #pragma unroll
            for (int e = 0; e < 2; e++){
                int chi = nb*8 + tg*2 + e;
                ca[nb*2+e] = asv[hidx*DH + chi];
                cd[nb*2+e] = adv[hidx*DH + chi];
            }
    }
    #pragma unroll
    for (int mb = 0; mb < 2; mb++){
        #pragma unroll
        for (int nb = 0; nb < NB; nb++){
            float* a_ = acc[mb][nb];
            int col = bn + wn + nb*8 + tg*2;
            #pragma unroll
            for (int half = 0; half < 2; half++){
                int r = bm + wm + mb*16 + g + half*8;
                size_t ci = (size_t)r*N + col;
                float v0 = a_[half*2], v1 = a_[half*2+1];
                if (EPI == 0 || EPI == 4){
                    *(float2*)&C[ci] = make_float2(v0, v1);
                    if (EPI == 4){
                        sacc[mb][half] = fmaf(v0, ca[nb*2], fmaf(v1, ca[nb*2+1], sacc[mb][half]));
                        dacc[mb][half] = fmaf(v0, cd[nb*2], fmaf(v1, cd[nb*2+1], dacc[mb][half]));
                    }
                } else if (EPI == 1){
                    v0 += bias[col]; v1 += bias[col+1];
                    float t0 = 0.7978845608028654f*(v0 + 0.044715f*v0*v0*v0);
                    v0 = 0.5f*v0*(1.f + tanhf(t0));
                    float t1 = 0.7978845608028654f*(v1 + 0.044715f*v1*v1*v1);
                    v1 = 0.5f*v1*(1.f + tanhf(t1));
                    __nv_bfloat16 h0,l0,h1,l1;
                    split_val(v0,h0,l0); split_val(v1,h1,l1);
                    __nv_bfloat162 hp2; hp2.x=h0; hp2.y=h1;
                    __nv_bfloat162 lp2; lp2.x=l0; lp2.y=l1;
                    *(__nv_bfloat162*)&Chi[ci] = hp2;
                    *(__nv_bfloat162*)&Clo[ci] = lp2;
                } else if (EPI == 2){
                    float2 rr = *(const float2*)&res[ci];
                    *(float2*)&C[ci] = make_float2(v0 + bias[col] + rr.x, v1 + bias[col+1] + rr.y);
                } else {
                    float2 rr = *(const float2*)&res[ci];
                    *(float2*)&C[ci] = make_float2(v0 + rr.x, v1 + rr.y);
                }
            }
        }
    }
    if (EPI == 4){
        #pragma unroll
        for (int mb = 0; mb < 2; mb++)
            #pragma unroll
            for (int half = 0; half < 2; half++){
                float s = sacc[mb][half], d = dacc[mb][half];
                s += __shfl_xor_sync(0xffffffffu, s, 1);
                s += __shfl_xor_sync(0xffffffffu, s, 2);
                d += __shfl_xor_sync(0xffffffffu, d, 1);
                d += __shfl_xor_sync(0xffffffffu, d, 2);
                if (tg == 0){
                    int r = bm + wm + mb*16 + g + half*8;
                    g_src[r*NH + hidx] = s;
                    g_dst[r*NH + hidx] = d;
                }
            }
    }
}

// ---------------- merged prep: transposes + split_x + va + build_nbr --------------
__device__ __forceinline__ void trans_tile(const float* __restrict__ inp, int ldi,
                                           __nv_bfloat16* __restrict__ oh, __nv_bfloat16* __restrict__ ol,
                                           int ldo, int kt, int nt, float scale){
    __shared__ float tile[32][33];
    int tx = threadIdx.x & 31, ty0 = threadIdx.x >> 5;
    #pragma unroll
    for (int i = 0; i < 4; i++){
        int ty = ty0 + i*8;
        tile[ty][tx] = inp[(size_t)(kt*32 + ty)*ldi + nt*32 + tx];
    }
    __syncthreads();
    #pragma unroll
    for (int i = 0; i < 4; i++){
        int ty = ty0 + i*8;
        float v = scale * tile[tx][ty];
        size_t oi = (size_t)(nt*32 + ty)*ldo + kt*32 + tx;
        __nv_bfloat16 hi, lo; split_val(v, hi, lo);
        oh[oi] = hi; ol[oi] = lo;
    }
}

__global__ __launch_bounds__(256)
void prep(const float* __restrict__ W0, const float* __restrict__ W1, const float* __restrict__ W2,
          const float* __restrict__ F1, const float* __restrict__ F2,
          const float* __restrict__ x,
          const float* __restrict__ as2, const float* __restrict__ ad2,
          const float* __restrict__ adj){
    int b = blockIdx.x, tid = threadIdx.x;
    if (b < 64){
        trans_tile(W0, DIM, w0_hi, w0_lo, DIM, b >> 3, b & 7, 1.f);
    } else if (b < 128){
        int t = b - 64;
        trans_tile(W1, DIM, w1_hi, w1_lo, DIM, t >> 3, t & 7, 1.f);
    } else if (b < 640){
        int rel = b - 128, h = rel >> 6, t = rel & 63;
        trans_tile(W2 + h*DIM, HD2, w2_hi + h*DIM, w2_lo + h*DIM, HD2, t >> 3, t & 7, 0.125f);
    } else if (b < 768){
        int rel = b - 640;
        trans_tile(F1, FFH, f1_hi, f1_lo, DIM, rel >> 4, rel & 15, 1.f);
    } else if (b < 896){
        int rel = b - 768;
        trans_tile(F2, DIM, f2_hi, f2_lo, FFH, rel >> 3, rel & 7, 1.f);
    } else if (b < 1920){
        int idx4 = (b - 896)*256 + tid;          // 1M/4 float4s
        float4 v = *(const float4*)&x[idx4*4];
        __nv_bfloat16 h0,l0,h1,l1,h2,l2,h3,l3;
        split_val(v.x,h0,l0); split_val(v.y,h1,l1);
        split_val(v.z,h2,l2); split_val(v.w,h3,l3);
        __nv_bfloat162 ha; ha.x=h0; ha.y=h1;
        __nv_bfloat162 hb; hb.x=h2; hb.y=h3;
        __nv_bfloat162 la; la.x=l0; la.y=l1;
        __nv_bfloat162 lb; lb.x=l2; lb.y=l3;
        *(__nv_bfloat162*)&gA_hi[idx4*4]   = ha;
        *(__nv_bfloat162*)&gA_hi[idx4*4+2] = hb;
        *(__nv_bfloat162*)&gA_lo[idx4*4]   = la;
        *(__nv_bfloat162*)&gA_lo[idx4*4+2] = lb;
    } else if (b < 2176){
        int rel = b - 1920;
        int gw = rel*8 + (tid >> 5);
        int lane = tid & 31;
        int h = gw >> 8, c = gw & 255;
        float s = 0.f, t = 0.f;
        #pragma unroll
        for (int d = lane; d < DIM; d += 32){
            float wv = W2[(size_t)c*HD2 + h*DIM + d];
            s += wv * as2[h*DIM + d];
            t += wv * ad2[h*DIM + d];
        }
        #pragma unroll
        for (int o = 16; o > 0; o >>= 1){
            s += __shfl_down_sync(0xffffffffu, s, o);
            t += __shfl_down_sync(0xffffffffu, t, o);
        }
        if (lane == 0){ g_va_src[h*DIM + c] = s; g_va_dst[h*DIM + c] = t; }
    } else {
        int row = (b - 2176)*8 + (tid >> 5);
        int lane = tid & 31;
        const float* arow = adj + (size_t)row * SEQ;
        int cnt = 0;
        for (int base = 0; base < SEQ; base += 128){
            float vv[4];
            #pragma unroll
            for (int i = 0; i < 4; i++) vv[i] = arow[base + i*32 + lane];
            #pragma unroll
            for (int i = 0; i < 4; i++){
                bool p = vv[i] > 0.f;
                unsigned m = __ballot_sync(0xffffffffu, p);
                if (p){
                    int pos = cnt + __popc(m & ((1u << lane) - 1u));
                    if (pos < MAXN) g_nbr[row*MAXN + pos] = base + i*32 + lane;
                }
                cnt += __popc(m);
            }
        }
        if (lane == 0) g_cnt[row] = cnt < MAXN ? cnt : MAXN;
    }
}

// ---------------- softmax weights -------------------------------------------------
__device__ __forceinline__ void compute_weights(int row, int b, int cnt,
                                                const int* nbr, float* w, float* srcI,
                                                const float* __restrict__ srcA,
                                                const float* __restrict__ dstA){
    int tid = threadIdx.x;
    if (tid < NH) srcI[tid] = srcA[row*NH + tid];
    __syncthreads();
    for (int idx = tid; idx < cnt*NH; idx += 256){
        int n = idx >> 3, h = idx & 7;
        float e = srcI[h] + dstA[(size_t)(b*SEQ + nbr[n])*NH + h];
        w[n*NH + h] = e > 0.f ? e : 0.2f*e;
    }
    __syncthreads();
    int h = tid >> 5, lane = tid & 31;
    float m = -1e30f;
    for (int n = lane; n < cnt; n += 32) m = fmaxf(m, w[n*NH + h]);
    #pragma unroll
    for (int o = 16; o > 0; o >>= 1) m = fmaxf(m, __shfl_xor_sync(0xffffffffu, m, o));
    float ssum = 0.f;
    for (int n = lane; n < cnt; n += 32){
        float e = expf(w[n*NH + h] - m);
        w[n*NH + h] = e;
        ssum += e;
    }
    #pragma unroll
    for (int o = 16; o > 0; o >>= 1) ssum += __shfl_xor_sync(0xffffffffu, ssum, o);
    float inv = 1.f / ssum;
    for (int n = lane; n < cnt; n += 32) w[n*NH + h] *= inv;
    __syncthreads();
}

// aggregate + residual + ELU (+optionally fused layer-2 scores)
template<bool S2>
__global__ __launch_bounds__(256)
void attn01(const float* __restrict__ resid, float* __restrict__ out){
    int row = blockIdx.x;
    int b = row / SEQ;
    int tid = threadIdx.x;
    int cnt = g_cnt[row];
    __shared__ int   nbr[MAXN];
    __shared__ float w[MAXN*NH];
    __shared__ float srcI[NH];
    __shared__ float val[DIM];
    for (int n = tid; n < cnt; n += 256) nbr[n] = g_nbr[row*MAXN + n];
    __syncthreads();
    compute_weights(row, b, cnt, nbr, w, srcI, g_src, g_dst);
    int ch = tid;
    int hh = ch >> 5;
    float acc = 0.f;
    int n = 0;
    for (; n + 4 <= cnt; n += 4){
        int j0 = nbr[n], j1 = nbr[n+1], j2 = nbr[n+2], j3 = nbr[n+3];
        float v0 = g_hp[((size_t)(b*SEQ + j0))*DIM + ch];
        float v1 = g_hp[((size_t)(b*SEQ + j1))*DIM + ch];
        float v2 = g_hp[((size_t)(b*SEQ + j2))*DIM + ch];
        float v3 = g_hp[((size_t)(b*SEQ + j3))*DIM + ch];
        acc = fmaf(w[(n+0)*NH + hh], v0, acc);
        acc = fmaf(w[(n+1)*NH + hh], v1, acc);
        acc = fmaf(w[(n+2)*NH + hh], v2, acc);
        acc = fmaf(w[(n+3)*NH + hh], v3, acc);
    }
    for (; n < cnt; n++)
        acc = fmaf(w[n*NH + hh], g_hp[((size_t)(b*SEQ + nbr[n]))*DIM + ch], acc);
    size_t oi = (size_t)row*DIM + ch;
    float v = acc + resid[oi];
    v = v > 0.f ? v : expm1f(v);
    out[oi] = v;
    split_val(v, gA_hi[oi], gA_lo[oi]);
    if (S2){
        val[ch] = v;
        __syncthreads();
        int h = tid >> 5, lane = tid & 31;
        float s = 0.f, t = 0.f;
        #pragma unroll
        for (int d = lane; d < DIM; d += 32){
            float vd = val[d];
            s = fmaf(vd, g_va_src[h*DIM + d], s);
            t = fmaf(vd, g_va_dst[h*DIM + d], t);
        }
        #pragma unroll
        for (int o = 16; o > 0; o >>= 1){
            s += __shfl_down_sync(0xffffffffu, s, o);
            t += __shfl_down_sync(0xffffffffu, t, o);
        }
        if (lane == 0){ g_src2[row*NH + h] = s; g_dst2[row*NH + h] = t; }
    }
}

// layer 2: aggregate h per head
__global__ __launch_bounds__(256)
void attn2b(){
    int row = blockIdx.x;
    int b = row / SEQ;
    int tid = threadIdx.x;
    int cnt = g_cnt[row];
    __shared__ int   nbr[MAXN];
    __shared__ float w[MAXN*NH];
    __shared__ float srcI[NH];
    for (int n = tid; n < cnt; n += 256) nbr[n] = g_nbr[row*MAXN + n];
    __syncthreads();
    compute_weights(row, b, cnt, nbr, w, srcI, g_src2, g_dst2);
    int c = tid;
    float acc[NH] = {};
    int n = 0;
    for (; n + 2 <= cnt; n += 2){
        int j0 = nbr[n], j1 = nbr[n+1];
        float v0 = g_h[(size_t)(b*SEQ + j0)*DIM + c];
        float v1 = g_h[(size_t)(b*SEQ + j1)*DIM + c];
        const float* w0p = &w[n*NH];
        const float* w1p = &w[(n+1)*NH];
        #pragma unroll
        for (int h = 0; h < NH; h++){
            acc[h] = fmaf(w0p[h], v0, acc[h]);
            acc[h] = fmaf(w1p[h], v1, acc[h]);
        }
    }
    for (; n < cnt; n++){
        float v = g_h[(size_t)(b*SEQ + nbr[n])*DIM + c];
        const float* wp = &w[n*NH];
        #pragma unroll
        for (int h = 0; h < NH; h++) acc[h] = fmaf(wp[h], v, acc[h]);
    }
    #pragma unroll
    for (int h = 0; h < NH; h++){
        size_t oi = (size_t)row*HD2 + h*DIM + c;
        split_val(acc[h], gA_hi[oi], gA_lo[oi]);
    }
}

// ---------------- LayerNorm -------------------------------------------------------
__global__ void layernorm(const float* __restrict__ in,
                          const float* __restrict__ ln_g, const float* __restrict__ ln_b,
                          float* __restrict__ out){
    int row = blockIdx.x, tid = threadIdx.x;
    float v = in[(size_t)row*DIM + tid];
    __shared__ float red[8];
    __shared__ float mu, rstd;
    float s = v;
    #pragma unroll
    for (int o = 16; o > 0; o >>= 1) s += __shfl_xor_sync(0xffffffffu, s, o);
    if ((tid & 31) == 0) red[tid >> 5] = s;
    __syncthreads();
    if (tid == 0){ float t = 0.f; for (int i = 0; i < 8; i++) t += red[i]; mu = t / 256.f; }
    __syncthreads();
    float d = v - mu;
    s = d*d;
    #pragma unroll
    for (int o = 16; o > 0; o >>= 1) s += __shfl_xor_sync(0xffffffffu, s, o);
    if ((tid & 31) == 0) red[tid >> 5] = s;
    __syncthreads();
    if (tid == 0){ float t = 0.f; for (int i = 0; i < 8; i++) t += red[i]; rstd = rsqrtf(t/256.f + 1e-5f); }
    __syncthreads();
    size_t oi = (size_t)row*DIM + tid;
    float o = d*rstd*ln_g[tid] + ln_b[tid];
    out[oi] = o;
    split_val(o, gA_hi[oi], gA_lo[oi]);
}

// ---------------- launch ---------------------------------------------------------
extern "C" void kernel_launch(void* const* d_in, const int* in_sizes, int n_in,
                              void* d_out, int out_size){
    const float* adj    = (const float*)d_in[0];
    const float* x      = (const float*)d_in[1];
    const float* W0     = (const float*)d_in[2];
    const float* a_src0 = (const float*)d_in[3];
    const float* a_dst0 = (const float*)d_in[4];
    const float* W1     = (const float*)d_in[5];
    const float* a_src1 = (const float*)d_in[6];
    const float* a_dst1 = (const float*)d_in[7];
    const float* W2     = (const float*)d_in[8];
    const float* a_src2 = (const float*)d_in[9];
    const float* a_dst2 = (const float*)d_in[10];
    const float* ln_g   = (const float*)d_in[11];
    const float* ln_b   = (const float*)d_in[12];
    const float* ff_w1  = (const float*)d_in[13];
    const float* ff_b1  = (const float*)d_in[14];
    const float* ff_w2  = (const float*)d_in[15];
    const float* ff_b2  = (const float*)d_in[16];
    float* out = (float*)d_out;

    float *p_hp, *p_h, *p_tmp, *p_ln;
    __nv_bfloat16 *pAh, *pAl, *pFh, *pFl;
    __nv_bfloat16 *pw0h,*pw0l,*pw1h,*pw1l,*pw2h,*pw2l,*pf1h,*pf1l,*pf2h,*pf2l;
    cudaGetSymbolAddress((void**)&p_hp,  g_hp);
    cudaGetSymbolAddress((void**)&p_h,   g_h);
    cudaGetSymbolAddress((void**)&p_tmp, g_tmp);
    cudaGetSymbolAddress((void**)&p_ln,  g_ln);
    cudaGetSymbolAddress((void**)&pAh, gA_hi);  cudaGetSymbolAddress((void**)&pAl, gA_lo);
    cudaGetSymbolAddress((void**)&pFh, gF_hi);  cudaGetSymbolAddress((void**)&pFl, gF_lo);
    cudaGetSymbolAddress((void**)&pw0h, w0_hi); cudaGetSymbolAddress((void**)&pw0l, w0_lo);
    cudaGetSymbolAddress((void**)&pw1h, w1_hi); cudaGetSymbolAddress((void**)&pw1l, w1_lo);
    cudaGetSymbolAddress((void**)&pw2h, w2_hi); cudaGetSymbolAddress((void**)&pw2l, w2_lo);
    cudaGetSymbolAddress((void**)&pf1h, f1_hi); cudaGetSymbolAddress((void**)&pf1l, f1_lo);
    cudaGetSymbolAddress((void**)&pf2h, f2_hi); cudaGetSymbolAddress((void**)&pf2l, f2_lo);

    const int SM64  = 3*(2*128*40*2 + 2*64*40*2);    // 92160
    const int SM128 = 3*(2*128*40*2 + 2*128*40*2);   // 122880
    cudaFuncSetAttribute(gemm_mma<4,64>,  cudaFuncAttributeMaxDynamicSharedMemorySize, SM64);
    cudaFuncSetAttribute(gemm_mma<3,64>,  cudaFuncAttributeMaxDynamicSharedMemorySize, SM64);
    cudaFuncSetAttribute(gemm_mma<2,64>,  cudaFuncAttributeMaxDynamicSharedMemorySize, SM64);
    cudaFuncSetAttribute(gemm_mma<1,128>, cudaFuncAttributeMaxDynamicSharedMemorySize, SM128);

    dim3 blk(256);
    prep<<<2688, blk>>>(W0, W1, W2, ff_w1, ff_w2, x, a_src2, a_dst2, adj);

    // ---- GAT layer 0 (GEMM + fused scores) ----
    gemm_mma<4,64><<<dim3(4,32), blk, SM64>>>(pAh, pAl, pw0h, pw0l, nullptr, nullptr,
                                              a_src0, a_dst0, p_hp, nullptr, nullptr, ROWS, DIM, DIM);
    attn01<false><<<ROWS, blk>>>(x, p_h);

    // ---- GAT layer 1 (GEMM + fused scores; attn also emits layer-2 scores) ----
    gemm_mma<4,64><<<dim3(4,32), blk, SM64>>>(pAh, pAl, pw1h, pw1l, nullptr, nullptr,
                                              a_src1, a_dst1, p_hp, nullptr, nullptr, ROWS, DIM, DIM);
    attn01<true><<<ROWS, blk>>>(p_h, p_h);

    // ---- GAT layer 2 ----
    attn2b<<<ROWS, blk>>>();
    gemm_mma<3,64><<<dim3(4,32), blk, SM64>>>(pAh, pAl, pw2h, pw2l, nullptr, p_h,
                                              nullptr, nullptr, p_tmp, nullptr, nullptr, ROWS, DIM, HD2);

    // ---- LayerNorm ----
    layernorm<<<ROWS, blk>>>(p_tmp, ln_g, ln_b, p_ln);

    // ---- FFN ----
    gemm_mma<1,128><<<dim3(4,32), blk, SM128>>>(pAh, pAl, pf1h, pf1l, ff_b1, nullptr,
                                                nullptr, nullptr, nullptr, pFh, pFl, ROWS, FFH, DIM);
    gemm_mma<2,64><<<dim3(4,32), blk, SM64>>>(pFh, pFl, pf2h, pf2l, ff_b2, p_ln,
                                              nullptr, nullptr, out, nullptr, nullptr, ROWS, DIM, FFH);
}